// round 8
// baseline (speedup 1.0000x reference)
#include <cuda_runtime.h>
#include <cuda_fp16.h>
#include <cstdint>
#include <math.h>

// ---------------------------------------------------------------------------
// Problem constants
// ---------------------------------------------------------------------------
#define BATCH 8
#define WDIM 64
#define CC 512
#define C8 64
#define C2 256
#define NPIX 4096
#define NPOOL 1024
#define NCAT 384

// ---------------------------------------------------------------------------
// Scratch (device globals; allocation-free)
// ---------------------------------------------------------------------------
__device__ __half d_Xh[(long long)BATCH * NPIX * CC];     // 32 MB  x fp16
__device__ __half d_WcatT[NCAT * CC];                     // [384][512]
__device__ __half d_WoT[CC * C2];                         // [512][256]
__device__ __half d_Gh[(long long)BATCH * NPIX * C8];     // 4 MB   g full-res
__device__ __half d_Fh[BATCH * NPOOL * C8];               // 1 MB   pooled f [p][c]
__device__ __half d_Vth[BATCH * C2 * NPOOL];              // 4 MB   pooled h transposed [d][p]
__device__ __half d_Oh[(long long)BATCH * NPIX * C2];     // 16 MB  attention out

// ---------------------------------------------------------------------------
// Helpers
// ---------------------------------------------------------------------------
__device__ __forceinline__ uint32_t smem_u32(const void* p) {
    uint32_t a;
    asm("{ .reg .u64 t; cvta.to.shared.u64 t, %1; cvt.u32.u64 %0, t; }" : "=r"(a) : "l"(p));
    return a;
}
__device__ __forceinline__ void cp16(uint32_t dst, const void* src) {
    asm volatile("cp.async.cg.shared.global [%0], [%1], 16;" ::"r"(dst), "l"(src));
}
#define CP_COMMIT() asm volatile("cp.async.commit_group;" ::: "memory")
#define CP_WAIT0()  asm volatile("cp.async.wait_group 0;" ::: "memory")
#define CP_WAIT1()  asm volatile("cp.async.wait_group 1;" ::: "memory")

__device__ __forceinline__ void mma_f16(float* d, const uint32_t* a, const uint32_t* b) {
    asm volatile(
        "mma.sync.aligned.m16n8k16.row.col.f32.f16.f16.f32 "
        "{%0,%1,%2,%3}, {%4,%5,%6,%7}, {%8,%9}, {%0,%1,%2,%3};"
        : "+f"(d[0]), "+f"(d[1]), "+f"(d[2]), "+f"(d[3])
        : "r"(a[0]), "r"(a[1]), "r"(a[2]), "r"(a[3]), "r"(b[0]), "r"(b[1]));
}
__device__ __forceinline__ uint32_t pack2(float x, float y) {
    __half2 h = __floats2half2_rn(x, y);
    return *reinterpret_cast<uint32_t*>(&h);
}

// ---------------------------------------------------------------------------
// Shared GEMM config: CTA 256x64, BK=32 halfs, 8 warps (4m x 2n), 3 stages.
// ---------------------------------------------------------------------------
#define HSTR 40
#define HASTG (256 * HSTR * 2)
#define HBSTG (64 * HSTR * 2)
#define HGSTG (HASTG + HBSTG)
#define SMEM_TOTAL_G (3 * HGSTG)

// ---------------------------------------------------------------------------
// Projection GEMM + fused 2x2 max-pool epilogue.
// ---------------------------------------------------------------------------
#define CSTR 72

__global__ void __launch_bounds__(256, 2) gemm_proj()
{
    extern __shared__ __align__(16) char smem[];
    const int m0 = blockIdx.y * 256;
    const int n0 = blockIdx.x * 64;
    const int tid = threadIdx.x;
    const int wid = tid >> 5, lane = tid & 31;
    const int gid = lane >> 2, tig = lane & 3;
    const int wm = (wid & 3) * 64;
    const int wn = (wid >> 2) * 32;

    const __half* A = d_Xh;
    const __half* Bt = d_WcatT;
    const uint32_t sb = smem_u32(smem);
    const int KT = CC / 32;

    auto issue = [&](int kt, int s) {
        const uint32_t aB = sb + (uint32_t)(s * HGSTG);
        const uint32_t bB = aB + HASTG;
#pragma unroll
        for (int it = 0; it < 4; it++) {
            int idx = tid + it * 256;
            int r = idx >> 2, q = idx & 3;
            cp16(aB + (uint32_t)(r * 80 + q * 16),
                 A + (long long)(m0 + r) * CC + kt * 32 + q * 8);
        }
        {
            int r = tid >> 2, q = tid & 3;
            cp16(bB + (uint32_t)(r * 80 + q * 16),
                 Bt + (long long)(n0 + r) * CC + kt * 32 + q * 8);
        }
        CP_COMMIT();
    };

    float acc[4][4][4];
#pragma unroll
    for (int i = 0; i < 4; i++)
#pragma unroll
        for (int j = 0; j < 4; j++)
#pragma unroll
            for (int k = 0; k < 4; k++) acc[i][j][k] = 0.f;

    issue(0, 0);
    issue(1, 1);

    for (int kt = 0; kt < KT; kt++) {
        const int s = kt % 3;
        if (kt < KT - 1) CP_WAIT1(); else CP_WAIT0();
        __syncthreads();
        if (kt + 2 < KT) issue(kt + 2, (kt + 2) % 3);

        const uint32_t* AsU = (const uint32_t*)(smem + s * HGSTG);
        const uint32_t* BsU = (const uint32_t*)(smem + s * HGSTG + HASTG);

#pragma unroll
        for (int ks = 0; ks < 2; ks++) {
            uint32_t a[4][4], b[4][2];
#pragma unroll
            for (int mt = 0; mt < 4; mt++) {
                int w = (wm + mt * 16 + gid) * 20 + ks * 8 + tig;
                a[mt][0] = AsU[w];
                a[mt][1] = AsU[w + 8 * 20];
                a[mt][2] = AsU[w + 4];
                a[mt][3] = AsU[w + 8 * 20 + 4];
            }
#pragma unroll
            for (int nt = 0; nt < 4; nt++) {
                int w = (wn + nt * 8 + gid) * 20 + ks * 8 + tig;
                b[nt][0] = BsU[w];
                b[nt][1] = BsU[w + 4];
            }
#pragma unroll
            for (int mt = 0; mt < 4; mt++)
#pragma unroll
                for (int nt = 0; nt < 4; nt++)
                    mma_f16(acc[mt][nt], a[mt], b[nt]);
        }
    }

    __syncthreads();
    uint32_t* Cw = (uint32_t*)smem;
#pragma unroll
    for (int mt = 0; mt < 4; mt++)
#pragma unroll
        for (int h = 0; h < 2; h++) {
            int row = wm + mt * 16 + gid + h * 8;
#pragma unroll
            for (int nt = 0; nt < 4; nt++)
                Cw[row * (CSTR / 2) + wn / 2 + nt * 4 + tig] =
                    pack2(acc[mt][nt][h * 2], acc[mt][nt][h * 2 + 1]);
        }
    __syncthreads();

    const __half* Cs = (const __half*)smem;
    const int b = m0 >> 12;
    const int pix0 = m0 & 4095;
    const int pr0 = pix0 >> 7;

    if (n0 == 64) {
        __half* G = d_Gh + (long long)m0 * C8;
#pragma unroll
        for (int it = 0; it < 8; it++) {
            int idx = tid + it * 256;
            int row = idx >> 3, q = idx & 7;
            uint4 v = *reinterpret_cast<const uint4*>(&Cw[row * (CSTR / 2) + q * 4]);
            *reinterpret_cast<uint4*>(&G[row * C8 + q * 8]) = v;
        }
    } else if (n0 == 0) {
        __half* F = d_Fh + (b * NPOOL + pr0 * 32) * C8;
        const __half2* C2s = (const __half2*)Cs;
#pragma unroll
        for (int it = 0; it < 8; it++) {
            int idx = tid + it * 256;
            int p = idx >> 5, c2 = idx & 31;
            int base = ((p >> 5) * 2) * 64 + (p & 31) * 2;
            __half2 v0 = C2s[(base) * (CSTR / 2) + c2];
            __half2 v1 = C2s[(base + 1) * (CSTR / 2) + c2];
            __half2 v2 = C2s[(base + 64) * (CSTR / 2) + c2];
            __half2 v3 = C2s[(base + 65) * (CSTR / 2) + c2];
            __half2 v = __hmax2(__hmax2(v0, v1), __hmax2(v2, v3));
            *reinterpret_cast<__half2*>(&F[p * C8 + 2 * c2]) = v;
        }
    } else {
        int c = tid & 63;
        int pgrp = tid >> 6;
        int d = n0 - 128 + c;
        __half buf[16];
#pragma unroll
        for (int j = 0; j < 16; j++) {
            int p = pgrp * 16 + j;
            int base = ((p >> 5) * 2) * 64 + (p & 31) * 2;
            __half v0 = Cs[(base) * CSTR + c];
            __half v1 = Cs[(base + 1) * CSTR + c];
            __half v2 = Cs[(base + 64) * CSTR + c];
            __half v3 = Cs[(base + 65) * CSTR + c];
            buf[j] = __hmax(__hmax(v0, v1), __hmax(v2, v3));
        }
        __half* dst = d_Vth + ((long long)b * C2 + d) * NPOOL + pr0 * 32 + pgrp * 16;
        *reinterpret_cast<uint4*>(dst) = *reinterpret_cast<uint4*>(buf);
        *reinterpret_cast<uint4*>(dst + 8) = *reinterpret_cast<uint4*>(buf + 8);
    }
}

// ---------------------------------------------------------------------------
// Output GEMM: out = gamma * (Oh @ WoT^T) + x   (M=32768, N=512, K=256)
// ---------------------------------------------------------------------------
__global__ void __launch_bounds__(256, 2) gemm_out(
    const float* __restrict__ resid, const float* __restrict__ gamma,
    float* __restrict__ C)
{
    extern __shared__ __align__(16) char smem[];
    const int m0 = blockIdx.y * 256;
    const int n0 = blockIdx.x * 64;
    const int tid = threadIdx.x;
    const int wid = tid >> 5, lane = tid & 31;
    const int gid = lane >> 2, tig = lane & 3;
    const int wm = (wid & 3) * 64;
    const int wn = (wid >> 2) * 32;

    const __half* A = d_Oh;
    const __half* Bt = d_WoT;
    const uint32_t sb = smem_u32(smem);
    const int KT = C2 / 32;

    auto issue = [&](int kt, int s) {
        const uint32_t aB = sb + (uint32_t)(s * HGSTG);
        const uint32_t bB = aB + HASTG;
#pragma unroll
        for (int it = 0; it < 4; it++) {
            int idx = tid + it * 256;
            int r = idx >> 2, q = idx & 3;
            cp16(aB + (uint32_t)(r * 80 + q * 16),
                 A + (long long)(m0 + r) * C2 + kt * 32 + q * 8);
        }
        {
            int r = tid >> 2, q = tid & 3;
            cp16(bB + (uint32_t)(r * 80 + q * 16),
                 Bt + (long long)(n0 + r) * C2 + kt * 32 + q * 8);
        }
        CP_COMMIT();
    };

    float acc[4][4][4];
#pragma unroll
    for (int i = 0; i < 4; i++)
#pragma unroll
        for (int j = 0; j < 4; j++)
#pragma unroll
            for (int k = 0; k < 4; k++) acc[i][j][k] = 0.f;

    issue(0, 0);
    issue(1, 1);

    for (int kt = 0; kt < KT; kt++) {
        const int s = kt % 3;
        if (kt < KT - 1) CP_WAIT1(); else CP_WAIT0();
        __syncthreads();
        if (kt + 2 < KT) issue(kt + 2, (kt + 2) % 3);

        const uint32_t* AsU = (const uint32_t*)(smem + s * HGSTG);
        const uint32_t* BsU = (const uint32_t*)(smem + s * HGSTG + HASTG);

#pragma unroll
        for (int ks = 0; ks < 2; ks++) {
            uint32_t a[4][4], b[4][2];
#pragma unroll
            for (int mt = 0; mt < 4; mt++) {
                int w = (wm + mt * 16 + gid) * 20 + ks * 8 + tig;
                a[mt][0] = AsU[w];
                a[mt][1] = AsU[w + 8 * 20];
                a[mt][2] = AsU[w + 4];
                a[mt][3] = AsU[w + 8 * 20 + 4];
            }
#pragma unroll
            for (int nt = 0; nt < 4; nt++) {
                int w = (wn + nt * 8 + gid) * 20 + ks * 8 + tig;
                b[nt][0] = BsU[w];
                b[nt][1] = BsU[w + 4];
            }
#pragma unroll
            for (int mt = 0; mt < 4; mt++)
#pragma unroll
                for (int nt = 0; nt < 4; nt++)
                    mma_f16(acc[mt][nt], a[mt], b[nt]);
        }
    }

    const float gm = gamma[0];
#pragma unroll
    for (int mt = 0; mt < 4; mt++)
#pragma unroll
        for (int h = 0; h < 2; h++) {
            long long row = m0 + wm + mt * 16 + gid + h * 8;
#pragma unroll
            for (int nt = 0; nt < 4; nt++) {
                long long off = row * CC + n0 + wn + nt * 8 + 2 * tig;
                float2 rv = *reinterpret_cast<const float2*>(&resid[off]);
                float2 v;
                v.x = fmaf(gm, acc[mt][nt][h * 2], rv.x);
                v.y = fmaf(gm, acc[mt][nt][h * 2 + 1], rv.y);
                *reinterpret_cast<float2*>(&C[off]) = v;
            }
        }
}

// ---------------------------------------------------------------------------
// Flash attention: 512 thr, 128 q/CTA, 8 chunks of 128 keys.
// Single smem reduction round per chunk: publish (local max, local sum) per
// warp-group, combine everywhere, scale P by exp(m_loc - m_new) before write.
// Q/K rows: 72 halfs (36 words). P/V rows: 136 halfs (68 words).
// ---------------------------------------------------------------------------
#define FQ 128
#define CK 128
#define NCHUNK 8
// byte offsets
#define SM_Q 0
#define SM_K 18432
#define SM_P 36864
#define SM_V 71680
#define SM_RM 141312
#define SM_RS 143360
#define FLASH_SMEM 145408

__global__ void __launch_bounds__(512, 1) flash_h()
{
    extern __shared__ __align__(16) char fsm[];
    const uint32_t sb = smem_u32(fsm);

    const int b = blockIdx.y;
    const int q0 = blockIdx.x * FQ;
    const __half* Qg = d_Gh + ((long long)b * NPIX + q0) * C8;
    const __half* Fb = d_Fh + b * NPOOL * C8;
    const __half* Vtb = d_Vth + (long long)b * C2 * NPOOL;
    __half* Ob = d_Oh + (long long)b * NPIX * C2;

    const int tid = threadIdx.x;
    const int wid = tid >> 5, lane = tid & 31;
    const int gid = lane >> 2, tig = lane & 3;
    const int wm = (wid & 3) * 32;
    const int wgrp = wid >> 2;
    const int wnS = wgrp * 32;   // S col base within 128
    const int wnP = wgrp * 64;   // PV col base within 256

    auto issueK = [&](int c) {
#pragma unroll
        for (int it = 0; it < 2; it++) {
            int idx = tid + it * 512;
            int r = idx >> 3, q = idx & 7;
            cp16(sb + SM_K + (uint32_t)(r * 144 + q * 16),
                 Fb + (c * CK + r) * C8 + q * 8);
        }
        CP_COMMIT();
    };
    auto issueV = [&](int c) {
#pragma unroll
        for (int it = 0; it < 8; it++) {
            int idx = tid + it * 512;
            int r = idx >> 4, q = idx & 15;
            cp16(sb + SM_V + (uint32_t)(r * 272 + q * 16),
                 Vtb + (long long)r * NPOOL + c * CK + q * 8);
        }
        CP_COMMIT();
    };

    // prologue: Q+K0 one group, V0 another
    {
#pragma unroll
        for (int it = 0; it < 2; it++) {
            int idx = tid + it * 512;
            int r = idx >> 3, q = idx & 7;
            cp16(sb + SM_Q + (uint32_t)(r * 144 + q * 16),
                 Qg + (long long)r * C8 + q * 8);
        }
        issueK(0);
        issueV(0);
    }

    float accO[2][8][4];
#pragma unroll
    for (int m = 0; m < 2; m++)
#pragma unroll
        for (int n = 0; n < 8; n++)
#pragma unroll
            for (int k = 0; k < 4; k++) accO[m][n][k] = 0.f;
    float mR[2][2] = {{-1e30f, -1e30f}, {-1e30f, -1e30f}};
    float lR[2][2] = {{0.f, 0.f}, {0.f, 0.f}};

    const uint32_t* Qw = (const uint32_t*)(fsm + SM_Q);
    const uint32_t* Kw = (const uint32_t*)(fsm + SM_K);
    const uint32_t* Vw = (const uint32_t*)(fsm + SM_V);
    uint32_t* Pw = (uint32_t*)(fsm + SM_P);
    float* redm = (float*)(fsm + SM_RM);
    float* reds = (float*)(fsm + SM_RS);

    for (int c = 0; c < NCHUNK; c++) {
        CP_WAIT1();                    // K(c) ready
        __syncthreads();

        // ---- S = Q @ F^T : warp tile 32q x 32k ----
        float accS[2][4][4];
#pragma unroll
        for (int m = 0; m < 2; m++)
#pragma unroll
            for (int n = 0; n < 4; n++)
#pragma unroll
                for (int k = 0; k < 4; k++) accS[m][n][k] = 0.f;
#pragma unroll
        for (int ks = 0; ks < 4; ks++) {
            uint32_t a[2][4], bb[4][2];
#pragma unroll
            for (int mt = 0; mt < 2; mt++) {
                int w = (wm + mt * 16 + gid) * 36 + ks * 8 + tig;
                a[mt][0] = Qw[w];
                a[mt][1] = Qw[w + 8 * 36];
                a[mt][2] = Qw[w + 4];
                a[mt][3] = Qw[w + 8 * 36 + 4];
            }
#pragma unroll
            for (int nt = 0; nt < 4; nt++) {
                int w = (wnS + nt * 8 + gid) * 36 + ks * 8 + tig;
                bb[nt][0] = Kw[w];
                bb[nt][1] = Kw[w + 4];
            }
#pragma unroll
            for (int mt = 0; mt < 2; mt++)
#pragma unroll
                for (int nt = 0; nt < 4; nt++)
                    mma_f16(accS[mt][nt], a[mt], bb[nt]);
        }

        // ---- local (warp-group) max per row-half, shuffles only ----
        float mloc[2][2];
#pragma unroll
        for (int mt = 0; mt < 2; mt++) {
            float cl = -1e30f, ch = -1e30f;
#pragma unroll
            for (int nt = 0; nt < 4; nt++) {
                cl = fmaxf(cl, fmaxf(accS[mt][nt][0], accS[mt][nt][1]));
                ch = fmaxf(ch, fmaxf(accS[mt][nt][2], accS[mt][nt][3]));
            }
#pragma unroll
            for (int o = 1; o <= 2; o <<= 1) {
                cl = fmaxf(cl, __shfl_xor_sync(0xffffffffu, cl, o));
                ch = fmaxf(ch, __shfl_xor_sync(0xffffffffu, ch, o));
            }
            mloc[mt][0] = cl;
            mloc[mt][1] = ch;
        }

        // ---- exp with local max (in place), local sums ----
        float ps[2][2] = {{0.f, 0.f}, {0.f, 0.f}};
#pragma unroll
        for (int mt = 0; mt < 2; mt++)
#pragma unroll
            for (int nt = 0; nt < 4; nt++) {
                accS[mt][nt][0] = __expf(accS[mt][nt][0] - mloc[mt][0]);
                accS[mt][nt][1] = __expf(accS[mt][nt][1] - mloc[mt][0]);
                accS[mt][nt][2] = __expf(accS[mt][nt][2] - mloc[mt][1]);
                accS[mt][nt][3] = __expf(accS[mt][nt][3] - mloc[mt][1]);
                ps[mt][0] += accS[mt][nt][0] + accS[mt][nt][1];
                ps[mt][1] += accS[mt][nt][2] + accS[mt][nt][3];
            }
#pragma unroll
        for (int mt = 0; mt < 2; mt++) {
#pragma unroll
            for (int o = 1; o <= 2; o <<= 1) {
                ps[mt][0] += __shfl_xor_sync(0xffffffffu, ps[mt][0], o);
                ps[mt][1] += __shfl_xor_sync(0xffffffffu, ps[mt][1], o);
            }
            if (tig == 0) {
                int row = wm + mt * 16 + gid;
                redm[wgrp * FQ + row] = mloc[mt][0];
                redm[wgrp * FQ + row + 8] = mloc[mt][1];
                reds[wgrp * FQ + row] = ps[mt][0];
                reds[wgrp * FQ + row + 8] = ps[mt][1];
            }
        }
        __syncthreads();               // stats visible; S done reading K
        if (c + 1 < NCHUNK) issueK(c + 1);

        // ---- combine stats; compute rescale sc and own-P factor f ----
        float sc[2][2], f[2][2];
#pragma unroll
        for (int mt = 0; mt < 2; mt++)
#pragma unroll
            for (int h = 0; h < 2; h++) {
                int row = wm + mt * 16 + gid + h * 8;
                float m0v = redm[row], m1v = redm[FQ + row];
                float m2v = redm[2 * FQ + row], m3v = redm[3 * FQ + row];
                float Mc = fmaxf(fmaxf(m0v, m1v), fmaxf(m2v, m3v));
                float mn = fmaxf(mR[mt][h], Mc);
                float Lc = reds[row] * __expf(m0v - mn) +
                           reds[FQ + row] * __expf(m1v - mn) +
                           reds[2 * FQ + row] * __expf(m2v - mn) +
                           reds[3 * FQ + row] * __expf(m3v - mn);
                sc[mt][h] = __expf(mR[mt][h] - mn);
                lR[mt][h] = lR[mt][h] * sc[mt][h] + Lc;
                mR[mt][h] = mn;
                f[mt][h] = __expf(mloc[mt][h] - mn);
            }

        // ---- scale own P values and write to smem ----
#pragma unroll
        for (int mt = 0; mt < 2; mt++) {
            int row = wm + mt * 16 + gid;
#pragma unroll
            for (int nt = 0; nt < 4; nt++) {
                int w = row * 68 + wgrp * 16 + nt * 4 + tig;
                Pw[w] = pack2(accS[mt][nt][0] * f[mt][0], accS[mt][nt][1] * f[mt][0]);
                Pw[w + 8 * 68] = pack2(accS[mt][nt][2] * f[mt][1], accS[mt][nt][3] * f[mt][1]);
            }
        }

        // ---- rescale accO ----
#pragma unroll
        for (int mt = 0; mt < 2; mt++)
#pragma unroll
            for (int nt = 0; nt < 8; nt++) {
                accO[mt][nt][0] *= sc[mt][0];
                accO[mt][nt][1] *= sc[mt][0];
                accO[mt][nt][2] *= sc[mt][1];
                accO[mt][nt][3] *= sc[mt][1];
            }

        // ---- wait V(c); barrier also publishes P ----
        if (c + 1 < NCHUNK) CP_WAIT1(); else CP_WAIT0();
        __syncthreads();

        // ---- O += P @ V : 8 k-steps of 16 ----
#pragma unroll
        for (int ks = 0; ks < 8; ks++) {
            uint32_t a[2][4];
#pragma unroll
            for (int mt = 0; mt < 2; mt++) {
                int w = (wm + mt * 16 + gid) * 68 + ks * 8 + tig;
                a[mt][0] = Pw[w];
                a[mt][1] = Pw[w + 8 * 68];
                a[mt][2] = Pw[w + 4];
                a[mt][3] = Pw[w + 8 * 68 + 4];
            }
#pragma unroll
            for (int nt = 0; nt < 8; nt++) {
                uint32_t bb[2];
                int w = (wnP + nt * 8 + gid) * 68 + ks * 8 + tig;
                bb[0] = Vw[w];
                bb[1] = Vw[w + 4];
#pragma unroll
                for (int mt = 0; mt < 2; mt++)
                    mma_f16(accO[mt][nt], a[mt], bb);
            }
        }
        __syncthreads();               // PV done: V and P buffers free
        if (c + 1 < NCHUNK) issueV(c + 1);
    }

    // ---- finalize ----
#pragma unroll
    for (int mt = 0; mt < 2; mt++) {
        float il = 1.f / lR[mt][0], ih = 1.f / lR[mt][1];
        int row = q0 + wm + mt * 16 + gid;
#pragma unroll
        for (int nt = 0; nt < 8; nt++) {
            int col = wnP + nt * 8 + 2 * tig;
            *reinterpret_cast<uint32_t*>(&Ob[(long long)row * C2 + col]) =
                pack2(accO[mt][nt][0] * il, accO[mt][nt][1] * il);
            *reinterpret_cast<uint32_t*>(&Ob[(long long)(row + 8) * C2 + col]) =
                pack2(accO[mt][nt][2] * ih, accO[mt][nt][3] * ih);
        }
    }
}

// ---------------------------------------------------------------------------
// x -> fp16
// ---------------------------------------------------------------------------
__global__ void convert_x_kernel(const float* __restrict__ x)
{
    int idx = blockIdx.x * blockDim.x + threadIdx.x;
    const float4 v = reinterpret_cast<const float4*>(x)[idx];
    uint2 u;
    u.x = pack2(v.x, v.y);
    u.y = pack2(v.z, v.w);
    reinterpret_cast<uint2*>(d_Xh)[idx] = u;
}

// ---------------------------------------------------------------------------
// Weights: WcatT [384][512] fp16, WoT [512][256] fp16
// ---------------------------------------------------------------------------
__global__ void concat_w_kernel(const float* __restrict__ wf,
                                const float* __restrict__ wg,
                                const float* __restrict__ wh,
                                const float* __restrict__ wo)
{
    int idx = blockIdx.x * blockDim.x + threadIdx.x;
    const int n1 = NCAT * CC;
    if (idx < n1) {
        int j = idx / CC, k = idx % CC;
        float v;
        if (j < 64)       v = wf[k * C8 + j];
        else if (j < 128) v = wg[k * C8 + (j - 64)];
        else              v = wh[k * C2 + (j - 128)];
        d_WcatT[idx] = __float2half_rn(v);
    } else if (idx < n1 + CC * C2) {
        int i2 = idx - n1;
        int c = i2 / C2, d = i2 % C2;
        d_WoT[i2] = __float2half_rn(wo[d * CC + c]);
    }
}

// ---------------------------------------------------------------------------
// Launch
// ---------------------------------------------------------------------------
extern "C" void kernel_launch(void* const* d_in, const int* in_sizes, int n_in,
                              void* d_out, int out_size)
{
    const float* x     = (const float*)d_in[0];
    const float* wf    = (const float*)d_in[1];
    const float* wg    = (const float*)d_in[2];
    const float* wh    = (const float*)d_in[3];
    const float* wo    = (const float*)d_in[4];
    const float* gamma = (const float*)d_in[5];
    float* out = (float*)d_out;

    cudaFuncSetAttribute(gemm_proj,
                         cudaFuncAttributeMaxDynamicSharedMemorySize, SMEM_TOTAL_G);
    cudaFuncSetAttribute(gemm_out,
                         cudaFuncAttributeMaxDynamicSharedMemorySize, SMEM_TOTAL_G);
    cudaFuncSetAttribute(flash_h,
                         cudaFuncAttributeMaxDynamicSharedMemorySize, FLASH_SMEM);

    // 0) x -> fp16
    convert_x_kernel<<<(BATCH * NPIX * CC / 4 + 255) / 256, 256>>>(x);

    // 1) weights -> fp16 transposed
    concat_w_kernel<<<(NCAT * CC + CC * C2 + 255) / 256, 256>>>(wf, wg, wh, wo);

    // 2+3) projection GEMM with fused pooling epilogue
    gemm_proj<<<dim3(NCAT / 64, (BATCH * NPIX) / 256), 256, SMEM_TOTAL_G>>>();

    // 4-6) fused attention -> Oh fp16
    flash_h<<<dim3(NPIX / FQ, BATCH), 512, FLASH_SMEM>>>();

    // 7) out = gamma * (Oh @ wo) + x
    gemm_out<<<dim3(CC / 64, (BATCH * NPIX) / 256), 256, SMEM_TOTAL_G>>>(x, gamma, out);
}

// round 9
// speedup vs baseline: 1.1430x; 1.1430x over previous
#include <cuda_runtime.h>
#include <cuda_fp16.h>
#include <cstdint>
#include <math.h>

// ---------------------------------------------------------------------------
// Problem constants
// ---------------------------------------------------------------------------
#define BATCH 8
#define WDIM 64
#define CC 512
#define C8 64
#define C2 256
#define NPIX 4096
#define NPOOL 1024
#define NCAT 384

// ---------------------------------------------------------------------------
// Scratch (device globals; allocation-free)
// ---------------------------------------------------------------------------
__device__ __half d_Xh[(long long)BATCH * NPIX * CC];     // 32 MB  x fp16
__device__ __half d_WcatT[NCAT * CC];                     // [384][512]
__device__ __half d_WoT[CC * C2];                         // [512][256]
__device__ __half d_Gh[(long long)BATCH * NPIX * C8];     // 4 MB   g full-res
__device__ __half d_Fh[BATCH * NPOOL * C8];               // 1 MB   pooled f [p][c]
__device__ __half d_Vth[BATCH * C2 * NPOOL];              // 4 MB   pooled h transposed [d][p]
__device__ __half d_Oh[(long long)BATCH * NPIX * C2];     // 16 MB  attention out

// ---------------------------------------------------------------------------
// Helpers
// ---------------------------------------------------------------------------
__device__ __forceinline__ uint32_t smem_u32(const void* p) {
    uint32_t a;
    asm("{ .reg .u64 t; cvta.to.shared.u64 t, %1; cvt.u32.u64 %0, t; }" : "=r"(a) : "l"(p));
    return a;
}
__device__ __forceinline__ void cp16(uint32_t dst, const void* src) {
    asm volatile("cp.async.cg.shared.global [%0], [%1], 16;" ::"r"(dst), "l"(src));
}
#define CP_COMMIT() asm volatile("cp.async.commit_group;" ::: "memory")
#define CP_WAIT0()  asm volatile("cp.async.wait_group 0;" ::: "memory")
#define CP_WAIT1()  asm volatile("cp.async.wait_group 1;" ::: "memory")

__device__ __forceinline__ void mma_f16(float* d, const uint32_t* a, const uint32_t* b) {
    asm volatile(
        "mma.sync.aligned.m16n8k16.row.col.f32.f16.f16.f32 "
        "{%0,%1,%2,%3}, {%4,%5,%6,%7}, {%8,%9}, {%0,%1,%2,%3};"
        : "+f"(d[0]), "+f"(d[1]), "+f"(d[2]), "+f"(d[3])
        : "r"(a[0]), "r"(a[1]), "r"(a[2]), "r"(a[3]), "r"(b[0]), "r"(b[1]));
}
__device__ __forceinline__ void ldsm4(uint32_t* r, uint32_t a) {
    asm volatile("ldmatrix.sync.aligned.m8n8.x4.shared.b16 {%0,%1,%2,%3}, [%4];"
                 : "=r"(r[0]), "=r"(r[1]), "=r"(r[2]), "=r"(r[3]) : "r"(a));
}
__device__ __forceinline__ uint32_t pack2(float x, float y) {
    __half2 h = __floats2half2_rn(x, y);
    return *reinterpret_cast<uint32_t*>(&h);
}

// ---------------------------------------------------------------------------
// Shared GEMM config: CTA 256x64, BK=32 halfs, 8 warps (4m x 2n), 3 stages.
// Row stride 80 B (= 16 mod 128 ... 80: LDSM 8-row phases hit distinct banks).
// ---------------------------------------------------------------------------
#define HSTR 40
#define HASTG (256 * HSTR * 2)
#define HBSTG (64 * HSTR * 2)
#define HGSTG (HASTG + HBSTG)
#define SMEM_TOTAL_G (3 * HGSTG)

// ---------------------------------------------------------------------------
// Projection GEMM + fused 2x2 max-pool epilogue.
// ---------------------------------------------------------------------------
#define CSTR 72

__global__ void __launch_bounds__(256, 2) gemm_proj()
{
    extern __shared__ __align__(16) char smem[];
    const int m0 = blockIdx.y * 256;
    const int n0 = blockIdx.x * 64;
    const int tid = threadIdx.x;
    const int wid = tid >> 5, lane = tid & 31;
    const int gid = lane >> 2, tig = lane & 3;
    const int wm = (wid & 3) * 64;
    const int wn = (wid >> 2) * 32;

    const __half* A = d_Xh;
    const __half* Bt = d_WcatT;
    const uint32_t sb = smem_u32(smem);
    const int KT = CC / 32;

    // per-lane ldmatrix offsets (bytes within stage)
    const int arow = lane & 15;
    const int acol = (lane >> 4) << 4;
    const int brow = (lane & 7) + ((lane >> 4) & 1) * 8;
    const int bcol = ((lane >> 3) & 1) << 4;
    uint32_t aoff[4], boff[2];
#pragma unroll
    for (int mt = 0; mt < 4; mt++) aoff[mt] = (uint32_t)((wm + mt * 16 + arow) * 80 + acol);
#pragma unroll
    for (int p = 0; p < 2; p++) boff[p] = (uint32_t)(HASTG + (wn + p * 16 + brow) * 80 + bcol);

    auto issue = [&](int kt, int s) {
        const uint32_t aB = sb + (uint32_t)(s * HGSTG);
        const uint32_t bB = aB + HASTG;
#pragma unroll
        for (int it = 0; it < 4; it++) {
            int idx = tid + it * 256;
            int r = idx >> 2, q = idx & 3;
            cp16(aB + (uint32_t)(r * 80 + q * 16),
                 A + (long long)(m0 + r) * CC + kt * 32 + q * 8);
        }
        {
            int r = tid >> 2, q = tid & 3;
            cp16(bB + (uint32_t)(r * 80 + q * 16),
                 Bt + (long long)(n0 + r) * CC + kt * 32 + q * 8);
        }
        CP_COMMIT();
    };

    float acc[4][4][4];
#pragma unroll
    for (int i = 0; i < 4; i++)
#pragma unroll
        for (int j = 0; j < 4; j++)
#pragma unroll
            for (int k = 0; k < 4; k++) acc[i][j][k] = 0.f;

    issue(0, 0);
    issue(1, 1);

    for (int kt = 0; kt < KT; kt++) {
        const int s = kt % 3;
        if (kt < KT - 1) CP_WAIT1(); else CP_WAIT0();
        __syncthreads();
        if (kt + 2 < KT) issue(kt + 2, (kt + 2) % 3);

        const uint32_t stB = sb + (uint32_t)(s * HGSTG);
#pragma unroll
        for (int ks = 0; ks < 2; ks++) {
            uint32_t a[4][4], b[4][2];
#pragma unroll
            for (int mt = 0; mt < 4; mt++) ldsm4(a[mt], stB + aoff[mt] + ks * 32);
#pragma unroll
            for (int p = 0; p < 2; p++) {
                uint32_t t[4];
                ldsm4(t, stB + boff[p] + ks * 32);
                b[2 * p][0] = t[0]; b[2 * p][1] = t[1];
                b[2 * p + 1][0] = t[2]; b[2 * p + 1][1] = t[3];
            }
#pragma unroll
            for (int mt = 0; mt < 4; mt++)
#pragma unroll
                for (int nt = 0; nt < 4; nt++)
                    mma_f16(acc[mt][nt], a[mt], b[nt]);
        }
    }

    __syncthreads();
    uint32_t* Cw = (uint32_t*)smem;
#pragma unroll
    for (int mt = 0; mt < 4; mt++)
#pragma unroll
        for (int h = 0; h < 2; h++) {
            int row = wm + mt * 16 + gid + h * 8;
#pragma unroll
            for (int nt = 0; nt < 4; nt++)
                Cw[row * (CSTR / 2) + wn / 2 + nt * 4 + tig] =
                    pack2(acc[mt][nt][h * 2], acc[mt][nt][h * 2 + 1]);
        }
    __syncthreads();

    const __half* Cs = (const __half*)smem;
    const int b = m0 >> 12;
    const int pix0 = m0 & 4095;
    const int pr0 = pix0 >> 7;

    if (n0 == 64) {
        __half* G = d_Gh + (long long)m0 * C8;
#pragma unroll
        for (int it = 0; it < 8; it++) {
            int idx = tid + it * 256;
            int row = idx >> 3, q = idx & 7;
            uint4 v = *reinterpret_cast<const uint4*>(&Cw[row * (CSTR / 2) + q * 4]);
            *reinterpret_cast<uint4*>(&G[row * C8 + q * 8]) = v;
        }
    } else if (n0 == 0) {
        __half* F = d_Fh + (b * NPOOL + pr0 * 32) * C8;
        const __half2* C2s = (const __half2*)Cs;
#pragma unroll
        for (int it = 0; it < 8; it++) {
            int idx = tid + it * 256;
            int p = idx >> 5, c2 = idx & 31;
            int base = ((p >> 5) * 2) * 64 + (p & 31) * 2;
            __half2 v0 = C2s[(base) * (CSTR / 2) + c2];
            __half2 v1 = C2s[(base + 1) * (CSTR / 2) + c2];
            __half2 v2 = C2s[(base + 64) * (CSTR / 2) + c2];
            __half2 v3 = C2s[(base + 65) * (CSTR / 2) + c2];
            __half2 v = __hmax2(__hmax2(v0, v1), __hmax2(v2, v3));
            *reinterpret_cast<__half2*>(&F[p * C8 + 2 * c2]) = v;
        }
    } else {
        int c = tid & 63;
        int pgrp = tid >> 6;
        int d = n0 - 128 + c;
        __half buf[16];
#pragma unroll
        for (int j = 0; j < 16; j++) {
            int p = pgrp * 16 + j;
            int base = ((p >> 5) * 2) * 64 + (p & 31) * 2;
            __half v0 = Cs[(base) * CSTR + c];
            __half v1 = Cs[(base + 1) * CSTR + c];
            __half v2 = Cs[(base + 64) * CSTR + c];
            __half v3 = Cs[(base + 65) * CSTR + c];
            buf[j] = __hmax(__hmax(v0, v1), __hmax(v2, v3));
        }
        __half* dst = d_Vth + ((long long)b * C2 + d) * NPOOL + pr0 * 32 + pgrp * 16;
        *reinterpret_cast<uint4*>(dst) = *reinterpret_cast<uint4*>(buf);
        *reinterpret_cast<uint4*>(dst + 8) = *reinterpret_cast<uint4*>(buf + 8);
    }
}

// ---------------------------------------------------------------------------
// Output GEMM: out = gamma * (Oh @ WoT^T) + x   (M=32768, N=512, K=256)
// ---------------------------------------------------------------------------
__global__ void __launch_bounds__(256, 2) gemm_out(
    const float* __restrict__ resid, const float* __restrict__ gamma,
    float* __restrict__ C)
{
    extern __shared__ __align__(16) char smem[];
    const int m0 = blockIdx.y * 256;
    const int n0 = blockIdx.x * 64;
    const int tid = threadIdx.x;
    const int wid = tid >> 5, lane = tid & 31;
    const int gid = lane >> 2, tig = lane & 3;
    const int wm = (wid & 3) * 64;
    const int wn = (wid >> 2) * 32;

    const __half* A = d_Oh;
    const __half* Bt = d_WoT;
    const uint32_t sb = smem_u32(smem);
    const int KT = C2 / 32;

    const int arow = lane & 15;
    const int acol = (lane >> 4) << 4;
    const int brow = (lane & 7) + ((lane >> 4) & 1) * 8;
    const int bcol = ((lane >> 3) & 1) << 4;
    uint32_t aoff[4], boff[2];
#pragma unroll
    for (int mt = 0; mt < 4; mt++) aoff[mt] = (uint32_t)((wm + mt * 16 + arow) * 80 + acol);
#pragma unroll
    for (int p = 0; p < 2; p++) boff[p] = (uint32_t)(HASTG + (wn + p * 16 + brow) * 80 + bcol);

    auto issue = [&](int kt, int s) {
        const uint32_t aB = sb + (uint32_t)(s * HGSTG);
        const uint32_t bB = aB + HASTG;
#pragma unroll
        for (int it = 0; it < 4; it++) {
            int idx = tid + it * 256;
            int r = idx >> 2, q = idx & 3;
            cp16(aB + (uint32_t)(r * 80 + q * 16),
                 A + (long long)(m0 + r) * C2 + kt * 32 + q * 8);
        }
        {
            int r = tid >> 2, q = tid & 3;
            cp16(bB + (uint32_t)(r * 80 + q * 16),
                 Bt + (long long)(n0 + r) * C2 + kt * 32 + q * 8);
        }
        CP_COMMIT();
    };

    float acc[4][4][4];
#pragma unroll
    for (int i = 0; i < 4; i++)
#pragma unroll
        for (int j = 0; j < 4; j++)
#pragma unroll
            for (int k = 0; k < 4; k++) acc[i][j][k] = 0.f;

    issue(0, 0);
    issue(1, 1);

    for (int kt = 0; kt < KT; kt++) {
        const int s = kt % 3;
        if (kt < KT - 1) CP_WAIT1(); else CP_WAIT0();
        __syncthreads();
        if (kt + 2 < KT) issue(kt + 2, (kt + 2) % 3);

        const uint32_t stB = sb + (uint32_t)(s * HGSTG);
#pragma unroll
        for (int ks = 0; ks < 2; ks++) {
            uint32_t a[4][4], b[4][2];
#pragma unroll
            for (int mt = 0; mt < 4; mt++) ldsm4(a[mt], stB + aoff[mt] + ks * 32);
#pragma unroll
            for (int p = 0; p < 2; p++) {
                uint32_t t[4];
                ldsm4(t, stB + boff[p] + ks * 32);
                b[2 * p][0] = t[0]; b[2 * p][1] = t[1];
                b[2 * p + 1][0] = t[2]; b[2 * p + 1][1] = t[3];
            }
#pragma unroll
            for (int mt = 0; mt < 4; mt++)
#pragma unroll
                for (int nt = 0; nt < 4; nt++)
                    mma_f16(acc[mt][nt], a[mt], b[nt]);
        }
    }

    const float gm = gamma[0];
#pragma unroll
    for (int mt = 0; mt < 4; mt++)
#pragma unroll
        for (int h = 0; h < 2; h++) {
            long long row = m0 + wm + mt * 16 + gid + h * 8;
#pragma unroll
            for (int nt = 0; nt < 4; nt++) {
                long long off = row * CC + n0 + wn + nt * 8 + 2 * tig;
                float2 rv = *reinterpret_cast<const float2*>(&resid[off]);
                float2 v;
                v.x = fmaf(gm, acc[mt][nt][h * 2], rv.x);
                v.y = fmaf(gm, acc[mt][nt][h * 2 + 1], rv.y);
                *reinterpret_cast<float2*>(&C[off]) = v;
            }
        }
}

// ---------------------------------------------------------------------------
// Flash attention (R7 structure + ldmatrix): 512 thr, 128 q/CTA, 16 chunks of 64.
// Rows 144 B everywhere (72 halfs) — conflict-free LDSM phases.
// ---------------------------------------------------------------------------
#define FQ 128
#define NCHUNK 16
#define SM_Q 0
#define SM_P 18432
#define SM_K 36864
#define SM_V 46080
#define SM_RM 82944
#define SM_RS 84992
#define FLASH_SMEM 87040

__global__ void __launch_bounds__(512, 1) flash_h()
{
    extern __shared__ __align__(16) char fsm[];
    const uint32_t sb = smem_u32(fsm);

    const int b = blockIdx.y;
    const int q0 = blockIdx.x * FQ;
    const __half* Qg = d_Gh + ((long long)b * NPIX + q0) * C8;
    const __half* Fb = d_Fh + b * NPOOL * C8;
    const __half* Vtb = d_Vth + (long long)b * C2 * NPOOL;
    __half* Ob = d_Oh + (long long)b * NPIX * C2;

    const int tid = threadIdx.x;
    const int wid = tid >> 5, lane = tid & 31;
    const int gid = lane >> 2, tig = lane & 3;
    const int wm = (wid & 3) * 32;
    const int wgrp = wid >> 2;
    const int wnS = wgrp * 16;
    const int wnP = wgrp * 64;

    // ldmatrix per-lane offsets
    const int arow = lane & 15;
    const int acol = (lane >> 4) << 4;
    const int brow = (lane & 7) + ((lane >> 4) & 1) * 8;
    const int bcol = ((lane >> 3) & 1) << 4;
    uint32_t qoff[2], poff[2], koff, voff[4];
#pragma unroll
    for (int mt = 0; mt < 2; mt++) {
        qoff[mt] = (uint32_t)(SM_Q + (wm + mt * 16 + arow) * 144 + acol);
        poff[mt] = (uint32_t)(SM_P + (wm + mt * 16 + arow) * 144 + acol);
    }
    koff = (uint32_t)(SM_K + (wnS + brow) * 144 + bcol);
#pragma unroll
    for (int p = 0; p < 4; p++)
        voff[p] = (uint32_t)(SM_V + (wnP + p * 16 + brow) * 144 + bcol);

    auto issueK = [&](int c) {
        int r = tid >> 3, q = tid & 7;
        cp16(sb + SM_K + (uint32_t)(r * 144 + q * 16),
             Fb + (c * 64 + r) * C8 + q * 8);
        CP_COMMIT();
    };
    auto issueV = [&](int c) {
#pragma unroll
        for (int it = 0; it < 4; it++) {
            int idx = tid + it * 512;
            int r = idx >> 3, q = idx & 7;
            cp16(sb + SM_V + (uint32_t)(r * 144 + q * 16),
                 Vtb + (long long)r * NPOOL + c * 64 + q * 8);
        }
        CP_COMMIT();
    };

    {
#pragma unroll
        for (int it = 0; it < 2; it++) {
            int idx = tid + it * 512;
            int r = idx >> 3, q = idx & 7;
            cp16(sb + SM_Q + (uint32_t)(r * 144 + q * 16),
                 Qg + (long long)r * C8 + q * 8);
        }
        issueK(0);
        issueV(0);
    }

    float accO[2][8][4];
#pragma unroll
    for (int m = 0; m < 2; m++)
#pragma unroll
        for (int n = 0; n < 8; n++)
#pragma unroll
            for (int k = 0; k < 4; k++) accO[m][n][k] = 0.f;
    float mM[2][2] = {{-1e30f, -1e30f}, {-1e30f, -1e30f}};
    float lL[2][2] = {{0.f, 0.f}, {0.f, 0.f}};

    uint32_t* Pw = (uint32_t*)(fsm + SM_P);
    float* redm = (float*)(fsm + SM_RM);
    float* reds = (float*)(fsm + SM_RS);

    for (int c = 0; c < NCHUNK; c++) {
        CP_WAIT1();
        __syncthreads();

        float accS[2][2][4];
#pragma unroll
        for (int m = 0; m < 2; m++)
#pragma unroll
            for (int n = 0; n < 2; n++)
#pragma unroll
                for (int k = 0; k < 4; k++) accS[m][n][k] = 0.f;
#pragma unroll
        for (int ks = 0; ks < 4; ks++) {
            uint32_t a[2][4], bb[2][2], t[4];
            ldsm4(a[0], sb + qoff[0] + ks * 32);
            ldsm4(a[1], sb + qoff[1] + ks * 32);
            ldsm4(t, sb + koff + ks * 32);
            bb[0][0] = t[0]; bb[0][1] = t[1];
            bb[1][0] = t[2]; bb[1][1] = t[3];
#pragma unroll
            for (int mt = 0; mt < 2; mt++)
#pragma unroll
                for (int nt = 0; nt < 2; nt++)
                    mma_f16(accS[mt][nt], a[mt], bb[nt]);
        }

#pragma unroll
        for (int mt = 0; mt < 2; mt++) {
            float cl = fmaxf(fmaxf(accS[mt][0][0], accS[mt][0][1]),
                             fmaxf(accS[mt][1][0], accS[mt][1][1]));
            float ch = fmaxf(fmaxf(accS[mt][0][2], accS[mt][0][3]),
                             fmaxf(accS[mt][1][2], accS[mt][1][3]));
#pragma unroll
            for (int o = 1; o <= 2; o <<= 1) {
                cl = fmaxf(cl, __shfl_xor_sync(0xffffffffu, cl, o));
                ch = fmaxf(ch, __shfl_xor_sync(0xffffffffu, ch, o));
            }
            if (tig == 0) {
                redm[wgrp * FQ + wm + mt * 16 + gid] = cl;
                redm[wgrp * FQ + wm + mt * 16 + gid + 8] = ch;
            }
        }
        __syncthreads();
        if (c + 1 < NCHUNK) issueK(c + 1);

        float sc[2][2];
#pragma unroll
        for (int mt = 0; mt < 2; mt++)
#pragma unroll
            for (int h = 0; h < 2; h++) {
                int row = wm + mt * 16 + gid + h * 8;
                float mc = fmaxf(fmaxf(redm[row], redm[FQ + row]),
                                 fmaxf(redm[2 * FQ + row], redm[3 * FQ + row]));
                float mn = fmaxf(mM[mt][h], mc);
                sc[mt][h] = __expf(mM[mt][h] - mn);
                mM[mt][h] = mn;
            }

        float ps[2][2] = {{0.f, 0.f}, {0.f, 0.f}};
#pragma unroll
        for (int mt = 0; mt < 2; mt++) {
            int row = wm + mt * 16 + gid;
#pragma unroll
            for (int nt = 0; nt < 2; nt++) {
                float e0 = __expf(accS[mt][nt][0] - mM[mt][0]);
                float e1 = __expf(accS[mt][nt][1] - mM[mt][0]);
                float e2 = __expf(accS[mt][nt][2] - mM[mt][1]);
                float e3 = __expf(accS[mt][nt][3] - mM[mt][1]);
                ps[mt][0] += e0 + e1;
                ps[mt][1] += e2 + e3;
                int w = row * 36 + wgrp * 8 + nt * 4 + tig;
                Pw[w] = pack2(e0, e1);
                Pw[w + 8 * 36] = pack2(e2, e3);
            }
        }
#pragma unroll
        for (int mt = 0; mt < 2; mt++) {
#pragma unroll
            for (int o = 1; o <= 2; o <<= 1) {
                ps[mt][0] += __shfl_xor_sync(0xffffffffu, ps[mt][0], o);
                ps[mt][1] += __shfl_xor_sync(0xffffffffu, ps[mt][1], o);
            }
            if (tig == 0) {
                reds[wgrp * FQ + wm + mt * 16 + gid] = ps[mt][0];
                reds[wgrp * FQ + wm + mt * 16 + gid + 8] = ps[mt][1];
            }
        }
        __syncthreads();
#pragma unroll
        for (int mt = 0; mt < 2; mt++)
#pragma unroll
            for (int h = 0; h < 2; h++) {
                int row = wm + mt * 16 + gid + h * 8;
                float su = reds[row] + reds[FQ + row] +
                           reds[2 * FQ + row] + reds[3 * FQ + row];
                lL[mt][h] = lL[mt][h] * sc[mt][h] + su;
            }

#pragma unroll
        for (int mt = 0; mt < 2; mt++)
#pragma unroll
            for (int nt = 0; nt < 8; nt++) {
                accO[mt][nt][0] *= sc[mt][0];
                accO[mt][nt][1] *= sc[mt][0];
                accO[mt][nt][2] *= sc[mt][1];
                accO[mt][nt][3] *= sc[mt][1];
            }

        if (c + 1 < NCHUNK) CP_WAIT1(); else CP_WAIT0();
        __syncthreads();

#pragma unroll
        for (int ks = 0; ks < 4; ks++) {
            uint32_t a[2][4];
            ldsm4(a[0], sb + poff[0] + ks * 32);
            ldsm4(a[1], sb + poff[1] + ks * 32);
#pragma unroll
            for (int p = 0; p < 4; p++) {
                uint32_t t[4], b0[2], b1[2];
                ldsm4(t, sb + voff[p] + ks * 32);
                b0[0] = t[0]; b0[1] = t[1];
                b1[0] = t[2]; b1[1] = t[3];
                mma_f16(accO[0][2 * p], a[0], b0);
                mma_f16(accO[1][2 * p], a[1], b0);
                mma_f16(accO[0][2 * p + 1], a[0], b1);
                mma_f16(accO[1][2 * p + 1], a[1], b1);
            }
        }
        __syncthreads();
        if (c + 1 < NCHUNK) issueV(c + 1);
    }

#pragma unroll
    for (int mt = 0; mt < 2; mt++) {
        float il = 1.f / lL[mt][0], ih = 1.f / lL[mt][1];
        int row = q0 + wm + mt * 16 + gid;
#pragma unroll
        for (int nt = 0; nt < 8; nt++) {
            int col = wnP + nt * 8 + 2 * tig;
            *reinterpret_cast<uint32_t*>(&Ob[(long long)row * C2 + col]) =
                pack2(accO[mt][nt][0] * il, accO[mt][nt][1] * il);
            *reinterpret_cast<uint32_t*>(&Ob[(long long)(row + 8) * C2 + col]) =
                pack2(accO[mt][nt][2] * ih, accO[mt][nt][3] * ih);
        }
    }
}

// ---------------------------------------------------------------------------
// x -> fp16
// ---------------------------------------------------------------------------
__global__ void convert_x_kernel(const float* __restrict__ x)
{
    int idx = blockIdx.x * blockDim.x + threadIdx.x;
    const float4 v = reinterpret_cast<const float4*>(x)[idx];
    uint2 u;
    u.x = pack2(v.x, v.y);
    u.y = pack2(v.z, v.w);
    reinterpret_cast<uint2*>(d_Xh)[idx] = u;
}

// ---------------------------------------------------------------------------
// Weights: WcatT [384][512] fp16, WoT [512][256] fp16
// ---------------------------------------------------------------------------
__global__ void concat_w_kernel(const float* __restrict__ wf,
                                const float* __restrict__ wg,
                                const float* __restrict__ wh,
                                const float* __restrict__ wo)
{
    int idx = blockIdx.x * blockDim.x + threadIdx.x;
    const int n1 = NCAT * CC;
    if (idx < n1) {
        int j = idx / CC, k = idx % CC;
        float v;
        if (j < 64)       v = wf[k * C8 + j];
        else if (j < 128) v = wg[k * C8 + (j - 64)];
        else              v = wh[k * C2 + (j - 128)];
        d_WcatT[idx] = __float2half_rn(v);
    } else if (idx < n1 + CC * C2) {
        int i2 = idx - n1;
        int c = i2 / C2, d = i2 % C2;
        d_WoT[i2] = __float2half_rn(wo[d * CC + c]);
    }
}

// ---------------------------------------------------------------------------
// Launch
// ---------------------------------------------------------------------------
extern "C" void kernel_launch(void* const* d_in, const int* in_sizes, int n_in,
                              void* d_out, int out_size)
{
    const float* x     = (const float*)d_in[0];
    const float* wf    = (const float*)d_in[1];
    const float* wg    = (const float*)d_in[2];
    const float* wh    = (const float*)d_in[3];
    const float* wo    = (const float*)d_in[4];
    const float* gamma = (const float*)d_in[5];
    float* out = (float*)d_out;

    cudaFuncSetAttribute(gemm_proj,
                         cudaFuncAttributeMaxDynamicSharedMemorySize, SMEM_TOTAL_G);
    cudaFuncSetAttribute(gemm_out,
                         cudaFuncAttributeMaxDynamicSharedMemorySize, SMEM_TOTAL_G);
    cudaFuncSetAttribute(flash_h,
                         cudaFuncAttributeMaxDynamicSharedMemorySize, FLASH_SMEM);

    // 0) x -> fp16
    convert_x_kernel<<<(BATCH * NPIX * CC / 4 + 255) / 256, 256>>>(x);

    // 1) weights -> fp16 transposed
    concat_w_kernel<<<(NCAT * CC + CC * C2 + 255) / 256, 256>>>(wf, wg, wh, wo);

    // 2+3) projection GEMM with fused pooling epilogue
    gemm_proj<<<dim3(NCAT / 64, (BATCH * NPIX) / 256), 256, SMEM_TOTAL_G>>>();

    // 4-6) fused attention -> Oh fp16
    flash_h<<<dim3(NPIX / FQ, BATCH), 512, FLASH_SMEM>>>();

    // 7) out = gamma * (Oh @ wo) + x
    gemm_out<<<dim3(CC / 64, (BATCH * NPIX) / 256), 256, SMEM_TOTAL_G>>>(x, gamma, out);
}

// round 10
// speedup vs baseline: 1.1531x; 1.0088x over previous
#include <cuda_runtime.h>
#include <cuda_fp16.h>
#include <cstdint>
#include <math.h>

// ---------------------------------------------------------------------------
// Problem constants
// ---------------------------------------------------------------------------
#define BATCH 8
#define WDIM 64
#define CC 512
#define C8 64
#define C2 256
#define NPIX 4096
#define NPOOL 1024
#define NCAT 384

// ---------------------------------------------------------------------------
// Scratch (device globals; allocation-free)
// ---------------------------------------------------------------------------
__device__ __half d_Xh[(long long)BATCH * NPIX * CC];     // 32 MB  x fp16
__device__ __half d_WcatT[NCAT * CC];                     // [384][512]
__device__ __half d_WoT[CC * C2];                         // [512][256]
__device__ __half d_Gh[(long long)BATCH * NPIX * C8];     // 4 MB   g full-res
__device__ __half d_Fh[BATCH * NPOOL * C8];               // 1 MB   pooled f [p][c]
__device__ __half d_Vth[BATCH * C2 * NPOOL];              // 4 MB   pooled h transposed [d][p]
__device__ __half d_Oh[(long long)BATCH * NPIX * C2];     // 16 MB  attention out

// ---------------------------------------------------------------------------
// Helpers
// ---------------------------------------------------------------------------
__device__ __forceinline__ uint32_t smem_u32(const void* p) {
    uint32_t a;
    asm("{ .reg .u64 t; cvta.to.shared.u64 t, %1; cvt.u32.u64 %0, t; }" : "=r"(a) : "l"(p));
    return a;
}
__device__ __forceinline__ void cp16(uint32_t dst, const void* src) {
    asm volatile("cp.async.cg.shared.global [%0], [%1], 16;" ::"r"(dst), "l"(src));
}
#define CP_COMMIT() asm volatile("cp.async.commit_group;" ::: "memory")
#define CP_WAIT0()  asm volatile("cp.async.wait_group 0;" ::: "memory")
#define CP_WAIT1()  asm volatile("cp.async.wait_group 1;" ::: "memory")

__device__ __forceinline__ void mma_f16(float* d, const uint32_t* a, const uint32_t* b) {
    asm volatile(
        "mma.sync.aligned.m16n8k16.row.col.f32.f16.f16.f32 "
        "{%0,%1,%2,%3}, {%4,%5,%6,%7}, {%8,%9}, {%0,%1,%2,%3};"
        : "+f"(d[0]), "+f"(d[1]), "+f"(d[2]), "+f"(d[3])
        : "r"(a[0]), "r"(a[1]), "r"(a[2]), "r"(a[3]), "r"(b[0]), "r"(b[1]));
}
__device__ __forceinline__ void ldsm4(uint32_t* r, uint32_t a) {
    asm volatile("ldmatrix.sync.aligned.m8n8.x4.shared.b16 {%0,%1,%2,%3}, [%4];"
                 : "=r"(r[0]), "=r"(r[1]), "=r"(r[2]), "=r"(r[3]) : "r"(a));
}
__device__ __forceinline__ uint32_t pack2(float x, float y) {
    __half2 h = __floats2half2_rn(x, y);
    return *reinterpret_cast<uint32_t*>(&h);
}
// fp16x2 exp2: one MUFU op for two values
__device__ __forceinline__ uint32_t ex2_h2(uint32_t in) {
    uint32_t r;
    asm("ex2.approx.f16x2 %0, %1;" : "=r"(r) : "r"(in));
    return r;
}
#define L2E 1.4426950408889634f

// ---------------------------------------------------------------------------
// Shared GEMM config: CTA 256x64, BK=32 halfs, 8 warps (4m x 2n), 3 stages.
// ---------------------------------------------------------------------------
#define HSTR 40
#define HASTG (256 * HSTR * 2)
#define HBSTG (64 * HSTR * 2)
#define HGSTG (HASTG + HBSTG)
#define SMEM_TOTAL_G (3 * HGSTG)

// ---------------------------------------------------------------------------
// Projection GEMM + fused 2x2 max-pool epilogue.
// ---------------------------------------------------------------------------
#define CSTR 72

__global__ void __launch_bounds__(256, 2) gemm_proj()
{
    extern __shared__ __align__(16) char smem[];
    const int m0 = blockIdx.y * 256;
    const int n0 = blockIdx.x * 64;
    const int tid = threadIdx.x;
    const int wid = tid >> 5, lane = tid & 31;
    const int gid = lane >> 2, tig = lane & 3;
    const int wm = (wid & 3) * 64;
    const int wn = (wid >> 2) * 32;

    const __half* A = d_Xh;
    const __half* Bt = d_WcatT;
    const uint32_t sb = smem_u32(smem);
    const int KT = CC / 32;

    const int arow = lane & 15;
    const int acol = (lane >> 4) << 4;
    const int brow = (lane & 7) + ((lane >> 4) & 1) * 8;
    const int bcol = ((lane >> 3) & 1) << 4;
    uint32_t aoff[4], boff[2];
#pragma unroll
    for (int mt = 0; mt < 4; mt++) aoff[mt] = (uint32_t)((wm + mt * 16 + arow) * 80 + acol);
#pragma unroll
    for (int p = 0; p < 2; p++) boff[p] = (uint32_t)(HASTG + (wn + p * 16 + brow) * 80 + bcol);

    auto issue = [&](int kt, int s) {
        const uint32_t aB = sb + (uint32_t)(s * HGSTG);
        const uint32_t bB = aB + HASTG;
#pragma unroll
        for (int it = 0; it < 4; it++) {
            int idx = tid + it * 256;
            int r = idx >> 2, q = idx & 3;
            cp16(aB + (uint32_t)(r * 80 + q * 16),
                 A + (long long)(m0 + r) * CC + kt * 32 + q * 8);
        }
        {
            int r = tid >> 2, q = tid & 3;
            cp16(bB + (uint32_t)(r * 80 + q * 16),
                 Bt + (long long)(n0 + r) * CC + kt * 32 + q * 8);
        }
        CP_COMMIT();
    };

    float acc[4][4][4];
#pragma unroll
    for (int i = 0; i < 4; i++)
#pragma unroll
        for (int j = 0; j < 4; j++)
#pragma unroll
            for (int k = 0; k < 4; k++) acc[i][j][k] = 0.f;

    issue(0, 0);
    issue(1, 1);

    for (int kt = 0; kt < KT; kt++) {
        const int s = kt % 3;
        if (kt < KT - 1) CP_WAIT1(); else CP_WAIT0();
        __syncthreads();
        if (kt + 2 < KT) issue(kt + 2, (kt + 2) % 3);

        const uint32_t stB = sb + (uint32_t)(s * HGSTG);
#pragma unroll
        for (int ks = 0; ks < 2; ks++) {
            uint32_t a[4][4], b[4][2];
#pragma unroll
            for (int mt = 0; mt < 4; mt++) ldsm4(a[mt], stB + aoff[mt] + ks * 32);
#pragma unroll
            for (int p = 0; p < 2; p++) {
                uint32_t t[4];
                ldsm4(t, stB + boff[p] + ks * 32);
                b[2 * p][0] = t[0]; b[2 * p][1] = t[1];
                b[2 * p + 1][0] = t[2]; b[2 * p + 1][1] = t[3];
            }
#pragma unroll
            for (int mt = 0; mt < 4; mt++)
#pragma unroll
                for (int nt = 0; nt < 4; nt++)
                    mma_f16(acc[mt][nt], a[mt], b[nt]);
        }
    }

    __syncthreads();
    uint32_t* Cw = (uint32_t*)smem;
#pragma unroll
    for (int mt = 0; mt < 4; mt++)
#pragma unroll
        for (int h = 0; h < 2; h++) {
            int row = wm + mt * 16 + gid + h * 8;
#pragma unroll
            for (int nt = 0; nt < 4; nt++)
                Cw[row * (CSTR / 2) + wn / 2 + nt * 4 + tig] =
                    pack2(acc[mt][nt][h * 2], acc[mt][nt][h * 2 + 1]);
        }
    __syncthreads();

    const __half* Cs = (const __half*)smem;
    const int b = m0 >> 12;
    const int pix0 = m0 & 4095;
    const int pr0 = pix0 >> 7;

    if (n0 == 64) {
        __half* G = d_Gh + (long long)m0 * C8;
#pragma unroll
        for (int it = 0; it < 8; it++) {
            int idx = tid + it * 256;
            int row = idx >> 3, q = idx & 7;
            uint4 v = *reinterpret_cast<const uint4*>(&Cw[row * (CSTR / 2) + q * 4]);
            *reinterpret_cast<uint4*>(&G[row * C8 + q * 8]) = v;
        }
    } else if (n0 == 0) {
        __half* F = d_Fh + (b * NPOOL + pr0 * 32) * C8;
        const __half2* C2s = (const __half2*)Cs;
#pragma unroll
        for (int it = 0; it < 8; it++) {
            int idx = tid + it * 256;
            int p = idx >> 5, c2 = idx & 31;
            int base = ((p >> 5) * 2) * 64 + (p & 31) * 2;
            __half2 v0 = C2s[(base) * (CSTR / 2) + c2];
            __half2 v1 = C2s[(base + 1) * (CSTR / 2) + c2];
            __half2 v2 = C2s[(base + 64) * (CSTR / 2) + c2];
            __half2 v3 = C2s[(base + 65) * (CSTR / 2) + c2];
            __half2 v = __hmax2(__hmax2(v0, v1), __hmax2(v2, v3));
            *reinterpret_cast<__half2*>(&F[p * C8 + 2 * c2]) = v;
        }
    } else {
        int c = tid & 63;
        int pgrp = tid >> 6;
        int d = n0 - 128 + c;
        __half buf[16];
#pragma unroll
        for (int j = 0; j < 16; j++) {
            int p = pgrp * 16 + j;
            int base = ((p >> 5) * 2) * 64 + (p & 31) * 2;
            __half v0 = Cs[(base) * CSTR + c];
            __half v1 = Cs[(base + 1) * CSTR + c];
            __half v2 = Cs[(base + 64) * CSTR + c];
            __half v3 = Cs[(base + 65) * CSTR + c];
            buf[j] = __hmax(__hmax(v0, v1), __hmax(v2, v3));
        }
        __half* dst = d_Vth + ((long long)b * C2 + d) * NPOOL + pr0 * 32 + pgrp * 16;
        *reinterpret_cast<uint4*>(dst) = *reinterpret_cast<uint4*>(buf);
        *reinterpret_cast<uint4*>(dst + 8) = *reinterpret_cast<uint4*>(buf + 8);
    }
}

// ---------------------------------------------------------------------------
// Output GEMM: out = gamma * (Oh @ WoT^T) + x   (M=32768, N=512, K=256)
// ---------------------------------------------------------------------------
__global__ void __launch_bounds__(256, 2) gemm_out(
    const float* __restrict__ resid, const float* __restrict__ gamma,
    float* __restrict__ C)
{
    extern __shared__ __align__(16) char smem[];
    const int m0 = blockIdx.y * 256;
    const int n0 = blockIdx.x * 64;
    const int tid = threadIdx.x;
    const int wid = tid >> 5, lane = tid & 31;
    const int gid = lane >> 2, tig = lane & 3;
    const int wm = (wid & 3) * 64;
    const int wn = (wid >> 2) * 32;

    const __half* A = d_Oh;
    const __half* Bt = d_WoT;
    const uint32_t sb = smem_u32(smem);
    const int KT = C2 / 32;

    const int arow = lane & 15;
    const int acol = (lane >> 4) << 4;
    const int brow = (lane & 7) + ((lane >> 4) & 1) * 8;
    const int bcol = ((lane >> 3) & 1) << 4;
    uint32_t aoff[4], boff[2];
#pragma unroll
    for (int mt = 0; mt < 4; mt++) aoff[mt] = (uint32_t)((wm + mt * 16 + arow) * 80 + acol);
#pragma unroll
    for (int p = 0; p < 2; p++) boff[p] = (uint32_t)(HASTG + (wn + p * 16 + brow) * 80 + bcol);

    auto issue = [&](int kt, int s) {
        const uint32_t aB = sb + (uint32_t)(s * HGSTG);
        const uint32_t bB = aB + HASTG;
#pragma unroll
        for (int it = 0; it < 4; it++) {
            int idx = tid + it * 256;
            int r = idx >> 2, q = idx & 3;
            cp16(aB + (uint32_t)(r * 80 + q * 16),
                 A + (long long)(m0 + r) * C2 + kt * 32 + q * 8);
        }
        {
            int r = tid >> 2, q = tid & 3;
            cp16(bB + (uint32_t)(r * 80 + q * 16),
                 Bt + (long long)(n0 + r) * C2 + kt * 32 + q * 8);
        }
        CP_COMMIT();
    };

    float acc[4][4][4];
#pragma unroll
    for (int i = 0; i < 4; i++)
#pragma unroll
        for (int j = 0; j < 4; j++)
#pragma unroll
            for (int k = 0; k < 4; k++) acc[i][j][k] = 0.f;

    issue(0, 0);
    issue(1, 1);

    for (int kt = 0; kt < KT; kt++) {
        const int s = kt % 3;
        if (kt < KT - 1) CP_WAIT1(); else CP_WAIT0();
        __syncthreads();
        if (kt + 2 < KT) issue(kt + 2, (kt + 2) % 3);

        const uint32_t stB = sb + (uint32_t)(s * HGSTG);
#pragma unroll
        for (int ks = 0; ks < 2; ks++) {
            uint32_t a[4][4], b[4][2];
#pragma unroll
            for (int mt = 0; mt < 4; mt++) ldsm4(a[mt], stB + aoff[mt] + ks * 32);
#pragma unroll
            for (int p = 0; p < 2; p++) {
                uint32_t t[4];
                ldsm4(t, stB + boff[p] + ks * 32);
                b[2 * p][0] = t[0]; b[2 * p][1] = t[1];
                b[2 * p + 1][0] = t[2]; b[2 * p + 1][1] = t[3];
            }
#pragma unroll
            for (int mt = 0; mt < 4; mt++)
#pragma unroll
                for (int nt = 0; nt < 4; nt++)
                    mma_f16(acc[mt][nt], a[mt], b[nt]);
        }
    }

    const float gm = gamma[0];
#pragma unroll
    for (int mt = 0; mt < 4; mt++)
#pragma unroll
        for (int h = 0; h < 2; h++) {
            long long row = m0 + wm + mt * 16 + gid + h * 8;
#pragma unroll
            for (int nt = 0; nt < 4; nt++) {
                long long off = row * CC + n0 + wn + nt * 8 + 2 * tig;
                float2 rv = *reinterpret_cast<const float2*>(&resid[off]);
                float2 v;
                v.x = fmaf(gm, acc[mt][nt][h * 2], rv.x);
                v.y = fmaf(gm, acc[mt][nt][h * 2 + 1], rv.y);
                *reinterpret_cast<float2*>(&C[off]) = v;
            }
        }
}

// ---------------------------------------------------------------------------
// Flash attention: 512 thr, 128 q/CTA, 16 chunks of 64; ldmatrix fragments;
// P computed with ex2.approx.f16x2 (2 scores per MUFU op).
// ---------------------------------------------------------------------------
#define FQ 128
#define NCHUNK 16
#define SM_Q 0
#define SM_P 18432
#define SM_K 36864
#define SM_V 46080
#define SM_RM 82944
#define SM_RS 84992
#define FLASH_SMEM 87040

__global__ void __launch_bounds__(512, 1) flash_h()
{
    extern __shared__ __align__(16) char fsm[];
    const uint32_t sb = smem_u32(fsm);

    const int b = blockIdx.y;
    const int q0 = blockIdx.x * FQ;
    const __half* Qg = d_Gh + ((long long)b * NPIX + q0) * C8;
    const __half* Fb = d_Fh + b * NPOOL * C8;
    const __half* Vtb = d_Vth + (long long)b * C2 * NPOOL;
    __half* Ob = d_Oh + (long long)b * NPIX * C2;

    const int tid = threadIdx.x;
    const int wid = tid >> 5, lane = tid & 31;
    const int gid = lane >> 2, tig = lane & 3;
    const int wm = (wid & 3) * 32;
    const int wgrp = wid >> 2;
    const int wnS = wgrp * 16;
    const int wnP = wgrp * 64;

    const int arow = lane & 15;
    const int acol = (lane >> 4) << 4;
    const int brow = (lane & 7) + ((lane >> 4) & 1) * 8;
    const int bcol = ((lane >> 3) & 1) << 4;
    uint32_t qoff[2], poff[2], koff, voff[4];
#pragma unroll
    for (int mt = 0; mt < 2; mt++) {
        qoff[mt] = (uint32_t)(SM_Q + (wm + mt * 16 + arow) * 144 + acol);
        poff[mt] = (uint32_t)(SM_P + (wm + mt * 16 + arow) * 144 + acol);
    }
    koff = (uint32_t)(SM_K + (wnS + brow) * 144 + bcol);
#pragma unroll
    for (int p = 0; p < 4; p++)
        voff[p] = (uint32_t)(SM_V + (wnP + p * 16 + brow) * 144 + bcol);

    auto issueK = [&](int c) {
        int r = tid >> 3, q = tid & 7;
        cp16(sb + SM_K + (uint32_t)(r * 144 + q * 16),
             Fb + (c * 64 + r) * C8 + q * 8);
        CP_COMMIT();
    };
    auto issueV = [&](int c) {
#pragma unroll
        for (int it = 0; it < 4; it++) {
            int idx = tid + it * 512;
            int r = idx >> 3, q = idx & 7;
            cp16(sb + SM_V + (uint32_t)(r * 144 + q * 16),
                 Vtb + (long long)r * NPOOL + c * 64 + q * 8);
        }
        CP_COMMIT();
    };

    {
#pragma unroll
        for (int it = 0; it < 2; it++) {
            int idx = tid + it * 512;
            int r = idx >> 3, q = idx & 7;
            cp16(sb + SM_Q + (uint32_t)(r * 144 + q * 16),
                 Qg + (long long)r * C8 + q * 8);
        }
        issueK(0);
        issueV(0);
    }

    float accO[2][8][4];
#pragma unroll
    for (int m = 0; m < 2; m++)
#pragma unroll
        for (int n = 0; n < 8; n++)
#pragma unroll
            for (int k = 0; k < 4; k++) accO[m][n][k] = 0.f;
    float mM[2][2] = {{-1e30f, -1e30f}, {-1e30f, -1e30f}};
    float lL[2][2] = {{0.f, 0.f}, {0.f, 0.f}};

    uint32_t* Pw = (uint32_t*)(fsm + SM_P);
    float* redm = (float*)(fsm + SM_RM);
    float* reds = (float*)(fsm + SM_RS);

    for (int c = 0; c < NCHUNK; c++) {
        CP_WAIT1();
        __syncthreads();

        float accS[2][2][4];
#pragma unroll
        for (int m = 0; m < 2; m++)
#pragma unroll
            for (int n = 0; n < 2; n++)
#pragma unroll
                for (int k = 0; k < 4; k++) accS[m][n][k] = 0.f;
#pragma unroll
        for (int ks = 0; ks < 4; ks++) {
            uint32_t a[2][4], bb[2][2], t[4];
            ldsm4(a[0], sb + qoff[0] + ks * 32);
            ldsm4(a[1], sb + qoff[1] + ks * 32);
            ldsm4(t, sb + koff + ks * 32);
            bb[0][0] = t[0]; bb[0][1] = t[1];
            bb[1][0] = t[2]; bb[1][1] = t[3];
#pragma unroll
            for (int mt = 0; mt < 2; mt++)
#pragma unroll
                for (int nt = 0; nt < 2; nt++)
                    mma_f16(accS[mt][nt], a[mt], bb[nt]);
        }

#pragma unroll
        for (int mt = 0; mt < 2; mt++) {
            float cl = fmaxf(fmaxf(accS[mt][0][0], accS[mt][0][1]),
                             fmaxf(accS[mt][1][0], accS[mt][1][1]));
            float ch = fmaxf(fmaxf(accS[mt][0][2], accS[mt][0][3]),
                             fmaxf(accS[mt][1][2], accS[mt][1][3]));
#pragma unroll
            for (int o = 1; o <= 2; o <<= 1) {
                cl = fmaxf(cl, __shfl_xor_sync(0xffffffffu, cl, o));
                ch = fmaxf(ch, __shfl_xor_sync(0xffffffffu, ch, o));
            }
            if (tig == 0) {
                redm[wgrp * FQ + wm + mt * 16 + gid] = cl;
                redm[wgrp * FQ + wm + mt * 16 + gid + 8] = ch;
            }
        }
        __syncthreads();
        if (c + 1 < NCHUNK) issueK(c + 1);

        float sc[2][2], nm[2][2];
#pragma unroll
        for (int mt = 0; mt < 2; mt++)
#pragma unroll
            for (int h = 0; h < 2; h++) {
                int row = wm + mt * 16 + gid + h * 8;
                float mc = fmaxf(fmaxf(redm[row], redm[FQ + row]),
                                 fmaxf(redm[2 * FQ + row], redm[3 * FQ + row]));
                float mn = fmaxf(mM[mt][h], mc);
                sc[mt][h] = __expf(mM[mt][h] - mn);
                mM[mt][h] = mn;
                nm[mt][h] = -mn * L2E;   // base-2 bias for fp16 exp
            }

        // ---- P = 2^(s*log2e - m*log2e) in fp16x2; row sums ----
        float ps[2][2] = {{0.f, 0.f}, {0.f, 0.f}};
#pragma unroll
        for (int mt = 0; mt < 2; mt++) {
            int row = wm + mt * 16 + gid;
#pragma unroll
            for (int nt = 0; nt < 2; nt++) {
                uint32_t e01 = ex2_h2(pack2(fmaf(accS[mt][nt][0], L2E, nm[mt][0]),
                                            fmaf(accS[mt][nt][1], L2E, nm[mt][0])));
                uint32_t e23 = ex2_h2(pack2(fmaf(accS[mt][nt][2], L2E, nm[mt][1]),
                                            fmaf(accS[mt][nt][3], L2E, nm[mt][1])));
                __half2 h01 = *reinterpret_cast<__half2*>(&e01);
                __half2 h23 = *reinterpret_cast<__half2*>(&e23);
                ps[mt][0] += __low2float(h01) + __high2float(h01);
                ps[mt][1] += __low2float(h23) + __high2float(h23);
                int w = row * 36 + wgrp * 8 + nt * 4 + tig;
                Pw[w] = e01;
                Pw[w + 8 * 36] = e23;
            }
        }
#pragma unroll
        for (int mt = 0; mt < 2; mt++) {
#pragma unroll
            for (int o = 1; o <= 2; o <<= 1) {
                ps[mt][0] += __shfl_xor_sync(0xffffffffu, ps[mt][0], o);
                ps[mt][1] += __shfl_xor_sync(0xffffffffu, ps[mt][1], o);
            }
            if (tig == 0) {
                reds[wgrp * FQ + wm + mt * 16 + gid] = ps[mt][0];
                reds[wgrp * FQ + wm + mt * 16 + gid + 8] = ps[mt][1];
            }
        }
        __syncthreads();
#pragma unroll
        for (int mt = 0; mt < 2; mt++)
#pragma unroll
            for (int h = 0; h < 2; h++) {
                int row = wm + mt * 16 + gid + h * 8;
                float su = reds[row] + reds[FQ + row] +
                           reds[2 * FQ + row] + reds[3 * FQ + row];
                lL[mt][h] = lL[mt][h] * sc[mt][h] + su;
            }

#pragma unroll
        for (int mt = 0; mt < 2; mt++)
#pragma unroll
            for (int nt = 0; nt < 8; nt++) {
                accO[mt][nt][0] *= sc[mt][0];
                accO[mt][nt][1] *= sc[mt][0];
                accO[mt][nt][2] *= sc[mt][1];
                accO[mt][nt][3] *= sc[mt][1];
            }

        if (c + 1 < NCHUNK) CP_WAIT1(); else CP_WAIT0();
        __syncthreads();

#pragma unroll
        for (int ks = 0; ks < 4; ks++) {
            uint32_t a[2][4];
            ldsm4(a[0], sb + poff[0] + ks * 32);
            ldsm4(a[1], sb + poff[1] + ks * 32);
#pragma unroll
            for (int p = 0; p < 4; p++) {
                uint32_t t[4], b0[2], b1[2];
                ldsm4(t, sb + voff[p] + ks * 32);
                b0[0] = t[0]; b0[1] = t[1];
                b1[0] = t[2]; b1[1] = t[3];
                mma_f16(accO[0][2 * p], a[0], b0);
                mma_f16(accO[1][2 * p], a[1], b0);
                mma_f16(accO[0][2 * p + 1], a[0], b1);
                mma_f16(accO[1][2 * p + 1], a[1], b1);
            }
        }
        __syncthreads();
        if (c + 1 < NCHUNK) issueV(c + 1);
    }

#pragma unroll
    for (int mt = 0; mt < 2; mt++) {
        float il = 1.f / lL[mt][0], ih = 1.f / lL[mt][1];
        int row = q0 + wm + mt * 16 + gid;
#pragma unroll
        for (int nt = 0; nt < 8; nt++) {
            int col = wnP + nt * 8 + 2 * tig;
            *reinterpret_cast<uint32_t*>(&Ob[(long long)row * C2 + col]) =
                pack2(accO[mt][nt][0] * il, accO[mt][nt][1] * il);
            *reinterpret_cast<uint32_t*>(&Ob[(long long)(row + 8) * C2 + col]) =
                pack2(accO[mt][nt][2] * ih, accO[mt][nt][3] * ih);
        }
    }
}

// ---------------------------------------------------------------------------
// x -> fp16
// ---------------------------------------------------------------------------
__global__ void convert_x_kernel(const float* __restrict__ x)
{
    int idx = blockIdx.x * blockDim.x + threadIdx.x;
    const float4 v = reinterpret_cast<const float4*>(x)[idx];
    uint2 u;
    u.x = pack2(v.x, v.y);
    u.y = pack2(v.z, v.w);
    reinterpret_cast<uint2*>(d_Xh)[idx] = u;
}

// ---------------------------------------------------------------------------
// Weights: WcatT [384][512] fp16, WoT [512][256] fp16
// ---------------------------------------------------------------------------
__global__ void concat_w_kernel(const float* __restrict__ wf,
                                const float* __restrict__ wg,
                                const float* __restrict__ wh,
                                const float* __restrict__ wo)
{
    int idx = blockIdx.x * blockDim.x + threadIdx.x;
    const int n1 = NCAT * CC;
    if (idx < n1) {
        int j = idx / CC, k = idx % CC;
        float v;
        if (j < 64)       v = wf[k * C8 + j];
        else if (j < 128) v = wg[k * C8 + (j - 64)];
        else              v = wh[k * C2 + (j - 128)];
        d_WcatT[idx] = __float2half_rn(v);
    } else if (idx < n1 + CC * C2) {
        int i2 = idx - n1;
        int c = i2 / C2, d = i2 % C2;
        d_WoT[i2] = __float2half_rn(wo[d * CC + c]);
    }
}

// ---------------------------------------------------------------------------
// Launch
// ---------------------------------------------------------------------------
extern "C" void kernel_launch(void* const* d_in, const int* in_sizes, int n_in,
                              void* d_out, int out_size)
{
    const float* x     = (const float*)d_in[0];
    const float* wf    = (const float*)d_in[1];
    const float* wg    = (const float*)d_in[2];
    const float* wh    = (const float*)d_in[3];
    const float* wo    = (const float*)d_in[4];
    const float* gamma = (const float*)d_in[5];
    float* out = (float*)d_out;

    cudaFuncSetAttribute(gemm_proj,
                         cudaFuncAttributeMaxDynamicSharedMemorySize, SMEM_TOTAL_G);
    cudaFuncSetAttribute(gemm_out,
                         cudaFuncAttributeMaxDynamicSharedMemorySize, SMEM_TOTAL_G);
    cudaFuncSetAttribute(flash_h,
                         cudaFuncAttributeMaxDynamicSharedMemorySize, FLASH_SMEM);

    // 0) x -> fp16
    convert_x_kernel<<<(BATCH * NPIX * CC / 4 + 255) / 256, 256>>>(x);

    // 1) weights -> fp16 transposed
    concat_w_kernel<<<(NCAT * CC + CC * C2 + 255) / 256, 256>>>(wf, wg, wh, wo);

    // 2+3) projection GEMM with fused pooling epilogue
    gemm_proj<<<dim3(NCAT / 64, (BATCH * NPIX) / 256), 256, SMEM_TOTAL_G>>>();

    // 4-6) fused attention -> Oh fp16
    flash_h<<<dim3(NPIX / FQ, BATCH), 512, FLASH_SMEM>>>();

    // 7) out = gamma * (Oh @ wo) + x
    gemm_out<<<dim3(CC / 64, (BATCH * NPIX) / 256), 256, SMEM_TOTAL_G>>>(x, gamma, out);
}

// round 11
// speedup vs baseline: 1.1719x; 1.0163x over previous
#include <cuda_runtime.h>
#include <cuda_fp16.h>
#include <cstdint>
#include <math.h>

// ---------------------------------------------------------------------------
// Problem constants
// ---------------------------------------------------------------------------
#define BATCH 8
#define WDIM 64
#define CC 512
#define C8 64
#define C2 256
#define NPIX 4096
#define NPOOL 1024
#define NCAT 384

// ---------------------------------------------------------------------------
// Scratch (device globals; allocation-free)
// ---------------------------------------------------------------------------
__device__ __half d_Xh[(long long)BATCH * NPIX * CC];     // 32 MB  x fp16
__device__ __half d_WcatT[NCAT * CC];                     // [384][512]
__device__ __half d_WoT[CC * C2];                         // [512][256]
__device__ __half d_Gh[(long long)BATCH * NPIX * C8];     // 4 MB   g full-res
__device__ __half d_Fh[BATCH * NPOOL * C8];               // 1 MB   pooled f [p][c]
__device__ __half d_Vth[BATCH * C2 * NPOOL];              // 4 MB   pooled h transposed [d][p]
__device__ __half d_Oh[(long long)BATCH * NPIX * C2];     // 16 MB  attention out

// ---------------------------------------------------------------------------
// Helpers
// ---------------------------------------------------------------------------
__device__ __forceinline__ uint32_t smem_u32(const void* p) {
    uint32_t a;
    asm("{ .reg .u64 t; cvta.to.shared.u64 t, %1; cvt.u32.u64 %0, t; }" : "=r"(a) : "l"(p));
    return a;
}
__device__ __forceinline__ void cp16(uint32_t dst, const void* src) {
    asm volatile("cp.async.cg.shared.global [%0], [%1], 16;" ::"r"(dst), "l"(src));
}
#define CP_COMMIT() asm volatile("cp.async.commit_group;" ::: "memory")
#define CP_WAIT0()  asm volatile("cp.async.wait_group 0;" ::: "memory")
#define CP_WAIT1()  asm volatile("cp.async.wait_group 1;" ::: "memory")

__device__ __forceinline__ void mma_f16(float* d, const uint32_t* a, const uint32_t* b) {
    asm volatile(
        "mma.sync.aligned.m16n8k16.row.col.f32.f16.f16.f32 "
        "{%0,%1,%2,%3}, {%4,%5,%6,%7}, {%8,%9}, {%0,%1,%2,%3};"
        : "+f"(d[0]), "+f"(d[1]), "+f"(d[2]), "+f"(d[3])
        : "r"(a[0]), "r"(a[1]), "r"(a[2]), "r"(a[3]), "r"(b[0]), "r"(b[1]));
}
__device__ __forceinline__ void ldsm4(uint32_t* r, uint32_t a) {
    asm volatile("ldmatrix.sync.aligned.m8n8.x4.shared.b16 {%0,%1,%2,%3}, [%4];"
                 : "=r"(r[0]), "=r"(r[1]), "=r"(r[2]), "=r"(r[3]) : "r"(a));
}
__device__ __forceinline__ uint32_t pack2(float x, float y) {
    __half2 h = __floats2half2_rn(x, y);
    return *reinterpret_cast<uint32_t*>(&h);
}
__device__ __forceinline__ uint32_t ex2_h2(uint32_t in) {
    uint32_t r;
    asm("ex2.approx.f16x2 %0, %1;" : "=r"(r) : "r"(in));
    return r;
}
#define L2E 1.4426950408889634f

// ---------------------------------------------------------------------------
// Shared GEMM config: CTA 256x64, BK=32 halfs, 8 warps (4m x 2n), 3 stages.
// ---------------------------------------------------------------------------
#define HSTR 40
#define HASTG (256 * HSTR * 2)
#define HBSTG (64 * HSTR * 2)
#define HGSTG (HASTG + HBSTG)
#define SMEM_TOTAL_G (3 * HGSTG)

// ---------------------------------------------------------------------------
// Projection GEMM + fused 2x2 max-pool epilogue.
// ---------------------------------------------------------------------------
#define CSTR 72

__global__ void __launch_bounds__(256, 2) gemm_proj()
{
    extern __shared__ __align__(16) char smem[];
    const int m0 = blockIdx.y * 256;
    const int n0 = blockIdx.x * 64;
    const int tid = threadIdx.x;
    const int wid = tid >> 5, lane = tid & 31;
    const int gid = lane >> 2, tig = lane & 3;
    const int wm = (wid & 3) * 64;
    const int wn = (wid >> 2) * 32;

    const __half* A = d_Xh;
    const __half* Bt = d_WcatT;
    const uint32_t sb = smem_u32(smem);
    const int KT = CC / 32;

    const int arow = lane & 15;
    const int acol = (lane >> 4) << 4;
    const int brow = (lane & 7) + ((lane >> 4) & 1) * 8;
    const int bcol = ((lane >> 3) & 1) << 4;
    uint32_t aoff[4], boff[2];
#pragma unroll
    for (int mt = 0; mt < 4; mt++) aoff[mt] = (uint32_t)((wm + mt * 16 + arow) * 80 + acol);
#pragma unroll
    for (int p = 0; p < 2; p++) boff[p] = (uint32_t)(HASTG + (wn + p * 16 + brow) * 80 + bcol);

    auto issue = [&](int kt, int s) {
        const uint32_t aB = sb + (uint32_t)(s * HGSTG);
        const uint32_t bB = aB + HASTG;
#pragma unroll
        for (int it = 0; it < 4; it++) {
            int idx = tid + it * 256;
            int r = idx >> 2, q = idx & 3;
            cp16(aB + (uint32_t)(r * 80 + q * 16),
                 A + (long long)(m0 + r) * CC + kt * 32 + q * 8);
        }
        {
            int r = tid >> 2, q = tid & 3;
            cp16(bB + (uint32_t)(r * 80 + q * 16),
                 Bt + (long long)(n0 + r) * CC + kt * 32 + q * 8);
        }
        CP_COMMIT();
    };

    float acc[4][4][4];
#pragma unroll
    for (int i = 0; i < 4; i++)
#pragma unroll
        for (int j = 0; j < 4; j++)
#pragma unroll
            for (int k = 0; k < 4; k++) acc[i][j][k] = 0.f;

    issue(0, 0);
    issue(1, 1);

    for (int kt = 0; kt < KT; kt++) {
        const int s = kt % 3;
        if (kt < KT - 1) CP_WAIT1(); else CP_WAIT0();
        __syncthreads();
        if (kt + 2 < KT) issue(kt + 2, (kt + 2) % 3);

        const uint32_t stB = sb + (uint32_t)(s * HGSTG);
#pragma unroll
        for (int ks = 0; ks < 2; ks++) {
            uint32_t a[4][4], b[4][2];
#pragma unroll
            for (int mt = 0; mt < 4; mt++) ldsm4(a[mt], stB + aoff[mt] + ks * 32);
#pragma unroll
            for (int p = 0; p < 2; p++) {
                uint32_t t[4];
                ldsm4(t, stB + boff[p] + ks * 32);
                b[2 * p][0] = t[0]; b[2 * p][1] = t[1];
                b[2 * p + 1][0] = t[2]; b[2 * p + 1][1] = t[3];
            }
#pragma unroll
            for (int mt = 0; mt < 4; mt++)
#pragma unroll
                for (int nt = 0; nt < 4; nt++)
                    mma_f16(acc[mt][nt], a[mt], b[nt]);
        }
    }

    __syncthreads();
    uint32_t* Cw = (uint32_t*)smem;
#pragma unroll
    for (int mt = 0; mt < 4; mt++)
#pragma unroll
        for (int h = 0; h < 2; h++) {
            int row = wm + mt * 16 + gid + h * 8;
#pragma unroll
            for (int nt = 0; nt < 4; nt++)
                Cw[row * (CSTR / 2) + wn / 2 + nt * 4 + tig] =
                    pack2(acc[mt][nt][h * 2], acc[mt][nt][h * 2 + 1]);
        }
    __syncthreads();

    const __half* Cs = (const __half*)smem;
    const int b = m0 >> 12;
    const int pix0 = m0 & 4095;
    const int pr0 = pix0 >> 7;

    if (n0 == 64) {
        __half* G = d_Gh + (long long)m0 * C8;
#pragma unroll
        for (int it = 0; it < 8; it++) {
            int idx = tid + it * 256;
            int row = idx >> 3, q = idx & 7;
            uint4 v = *reinterpret_cast<const uint4*>(&Cw[row * (CSTR / 2) + q * 4]);
            *reinterpret_cast<uint4*>(&G[row * C8 + q * 8]) = v;
        }
    } else if (n0 == 0) {
        __half* F = d_Fh + (b * NPOOL + pr0 * 32) * C8;
        const __half2* C2s = (const __half2*)Cs;
#pragma unroll
        for (int it = 0; it < 8; it++) {
            int idx = tid + it * 256;
            int p = idx >> 5, c2 = idx & 31;
            int base = ((p >> 5) * 2) * 64 + (p & 31) * 2;
            __half2 v0 = C2s[(base) * (CSTR / 2) + c2];
            __half2 v1 = C2s[(base + 1) * (CSTR / 2) + c2];
            __half2 v2 = C2s[(base + 64) * (CSTR / 2) + c2];
            __half2 v3 = C2s[(base + 65) * (CSTR / 2) + c2];
            __half2 v = __hmax2(__hmax2(v0, v1), __hmax2(v2, v3));
            *reinterpret_cast<__half2*>(&F[p * C8 + 2 * c2]) = v;
        }
    } else {
        int c = tid & 63;
        int pgrp = tid >> 6;
        int d = n0 - 128 + c;
        __half buf[16];
#pragma unroll
        for (int j = 0; j < 16; j++) {
            int p = pgrp * 16 + j;
            int base = ((p >> 5) * 2) * 64 + (p & 31) * 2;
            __half v0 = Cs[(base) * CSTR + c];
            __half v1 = Cs[(base + 1) * CSTR + c];
            __half v2 = Cs[(base + 64) * CSTR + c];
            __half v3 = Cs[(base + 65) * CSTR + c];
            buf[j] = __hmax(__hmax(v0, v1), __hmax(v2, v3));
        }
        __half* dst = d_Vth + ((long long)b * C2 + d) * NPOOL + pr0 * 32 + pgrp * 16;
        *reinterpret_cast<uint4*>(dst) = *reinterpret_cast<uint4*>(buf);
        *reinterpret_cast<uint4*>(dst + 8) = *reinterpret_cast<uint4*>(buf + 8);
    }
}

// ---------------------------------------------------------------------------
// Output GEMM: out = gamma * (Oh @ WoT^T) + x   (M=32768, N=512, K=256)
// ---------------------------------------------------------------------------
__global__ void __launch_bounds__(256, 2) gemm_out(
    const float* __restrict__ resid, const float* __restrict__ gamma,
    float* __restrict__ C)
{
    extern __shared__ __align__(16) char smem[];
    const int m0 = blockIdx.y * 256;
    const int n0 = blockIdx.x * 64;
    const int tid = threadIdx.x;
    const int wid = tid >> 5, lane = tid & 31;
    const int gid = lane >> 2, tig = lane & 3;
    const int wm = (wid & 3) * 64;
    const int wn = (wid >> 2) * 32;

    const __half* A = d_Oh;
    const __half* Bt = d_WoT;
    const uint32_t sb = smem_u32(smem);
    const int KT = C2 / 32;

    const int arow = lane & 15;
    const int acol = (lane >> 4) << 4;
    const int brow = (lane & 7) + ((lane >> 4) & 1) * 8;
    const int bcol = ((lane >> 3) & 1) << 4;
    uint32_t aoff[4], boff[2];
#pragma unroll
    for (int mt = 0; mt < 4; mt++) aoff[mt] = (uint32_t)((wm + mt * 16 + arow) * 80 + acol);
#pragma unroll
    for (int p = 0; p < 2; p++) boff[p] = (uint32_t)(HASTG + (wn + p * 16 + brow) * 80 + bcol);

    auto issue = [&](int kt, int s) {
        const uint32_t aB = sb + (uint32_t)(s * HGSTG);
        const uint32_t bB = aB + HASTG;
#pragma unroll
        for (int it = 0; it < 4; it++) {
            int idx = tid + it * 256;
            int r = idx >> 2, q = idx & 3;
            cp16(aB + (uint32_t)(r * 80 + q * 16),
                 A + (long long)(m0 + r) * C2 + kt * 32 + q * 8);
        }
        {
            int r = tid >> 2, q = tid & 3;
            cp16(bB + (uint32_t)(r * 80 + q * 16),
                 Bt + (long long)(n0 + r) * C2 + kt * 32 + q * 8);
        }
        CP_COMMIT();
    };

    float acc[4][4][4];
#pragma unroll
    for (int i = 0; i < 4; i++)
#pragma unroll
        for (int j = 0; j < 4; j++)
#pragma unroll
            for (int k = 0; k < 4; k++) acc[i][j][k] = 0.f;

    issue(0, 0);
    issue(1, 1);

    for (int kt = 0; kt < KT; kt++) {
        const int s = kt % 3;
        if (kt < KT - 1) CP_WAIT1(); else CP_WAIT0();
        __syncthreads();
        if (kt + 2 < KT) issue(kt + 2, (kt + 2) % 3);

        const uint32_t stB = sb + (uint32_t)(s * HGSTG);
#pragma unroll
        for (int ks = 0; ks < 2; ks++) {
            uint32_t a[4][4], b[4][2];
#pragma unroll
            for (int mt = 0; mt < 4; mt++) ldsm4(a[mt], stB + aoff[mt] + ks * 32);
#pragma unroll
            for (int p = 0; p < 2; p++) {
                uint32_t t[4];
                ldsm4(t, stB + boff[p] + ks * 32);
                b[2 * p][0] = t[0]; b[2 * p][1] = t[1];
                b[2 * p + 1][0] = t[2]; b[2 * p + 1][1] = t[3];
            }
#pragma unroll
            for (int mt = 0; mt < 4; mt++)
#pragma unroll
                for (int nt = 0; nt < 4; nt++)
                    mma_f16(acc[mt][nt], a[mt], b[nt]);
        }
    }

    const float gm = gamma[0];
#pragma unroll
    for (int mt = 0; mt < 4; mt++)
#pragma unroll
        for (int h = 0; h < 2; h++) {
            long long row = m0 + wm + mt * 16 + gid + h * 8;
#pragma unroll
            for (int nt = 0; nt < 4; nt++) {
                long long off = row * CC + n0 + wn + nt * 8 + 2 * tig;
                float2 rv = *reinterpret_cast<const float2*>(&resid[off]);
                float2 v;
                v.x = fmaf(gm, acc[mt][nt][h * 2], rv.x);
                v.y = fmaf(gm, acc[mt][nt][h * 2 + 1], rv.y);
                *reinterpret_cast<float2*>(&C[off]) = v;
            }
        }
}

// ---------------------------------------------------------------------------
// Flash attention: 256 thr / 64 q per CTA, 2 CTAs/SM, 16 chunks of 64 keys.
// 8 warps = 4m x 2 col-groups. Q fragments held in registers for all chunks.
// Smem/CTA = 64 KB: Q 9K | P 9K | K 9K | V 36K | stats 1K.
// ---------------------------------------------------------------------------
#define FQ 64
#define NCHUNK 16
#define SM_Q 0
#define SM_P 9216
#define SM_K 18432
#define SM_V 27648
#define SM_RM 64512
#define SM_RS 65024
#define FLASH_SMEM 65536

__global__ void __launch_bounds__(256, 2) flash_h()
{
    extern __shared__ __align__(16) char fsm[];
    const uint32_t sb = smem_u32(fsm);

    const int b = blockIdx.y;
    const int q0 = blockIdx.x * FQ;
    const __half* Qg = d_Gh + ((long long)b * NPIX + q0) * C8;
    const __half* Fb = d_Fh + b * NPOOL * C8;
    const __half* Vtb = d_Vth + (long long)b * C2 * NPOOL;
    __half* Ob = d_Oh + (long long)b * NPIX * C2;

    const int tid = threadIdx.x;
    const int wid = tid >> 5, lane = tid & 31;
    const int gid = lane >> 2, tig = lane & 3;
    const int wm = (wid & 3) * 16;     // 4 m-groups x 16 rows
    const int wgrp = wid >> 2;         // 2 col-groups
    const int wnS = wgrp * 32;         // keys 0-31 / 32-63
    const int wnP = wgrp * 128;        // PV cols

    const int arow = lane & 15;
    const int acol = (lane >> 4) << 4;
    const int brow = (lane & 7) + ((lane >> 4) & 1) * 8;
    const int bcol = ((lane >> 3) & 1) << 4;
    const uint32_t qoff = (uint32_t)(SM_Q + (wm + arow) * 144 + acol);
    const uint32_t poff = (uint32_t)(SM_P + (wm + arow) * 144 + acol);
    uint32_t koff[2], voff[8];
#pragma unroll
    for (int k16 = 0; k16 < 2; k16++)
        koff[k16] = (uint32_t)(SM_K + (wnS + k16 * 16 + brow) * 144 + bcol);
#pragma unroll
    for (int p = 0; p < 8; p++)
        voff[p] = (uint32_t)(SM_V + (wnP + p * 16 + brow) * 144 + bcol);

    auto issueK = [&](int c) {
#pragma unroll
        for (int it = 0; it < 2; it++) {
            int idx = tid + it * 256;
            int r = idx >> 3, q = idx & 7;
            cp16(sb + SM_K + (uint32_t)(r * 144 + q * 16),
                 Fb + (c * 64 + r) * C8 + q * 8);
        }
        CP_COMMIT();
    };
    auto issueV = [&](int c) {
#pragma unroll
        for (int it = 0; it < 8; it++) {
            int idx = tid + it * 256;
            int r = idx >> 3, q = idx & 7;
            cp16(sb + SM_V + (uint32_t)(r * 144 + q * 16),
                 Vtb + (long long)r * NPOOL + c * 64 + q * 8);
        }
        CP_COMMIT();
    };

    // prologue: Q + K0 one group, V0 another
    {
#pragma unroll
        for (int it = 0; it < 2; it++) {
            int idx = tid + it * 256;
            int r = idx >> 3, q = idx & 7;
            cp16(sb + SM_Q + (uint32_t)(r * 144 + q * 16),
                 Qg + (long long)r * C8 + q * 8);
        }
        issueK(0);   // commits Q + K0
        issueV(0);
    }

    // load Q fragments once (held for all chunks)
    CP_WAIT1();
    __syncthreads();
    uint32_t qf[4][4];
#pragma unroll
    for (int ks = 0; ks < 4; ks++) ldsm4(qf[ks], sb + qoff + ks * 32);

    float accO[16][4];
#pragma unroll
    for (int n = 0; n < 16; n++)
#pragma unroll
        for (int k = 0; k < 4; k++) accO[n][k] = 0.f;
    float mM[2] = {-1e30f, -1e30f};
    float lL[2] = {0.f, 0.f};

    uint32_t* Pw = (uint32_t*)(fsm + SM_P);
    float* redm = (float*)(fsm + SM_RM);
    float* reds = (float*)(fsm + SM_RS);

    for (int c = 0; c < NCHUNK; c++) {
        CP_WAIT1();                    // K(c) ready (V(c) may pend)
        __syncthreads();

        // ---- S = Q @ F^T : warp tile 16q x 32k ----
        float accS[4][4];
#pragma unroll
        for (int n = 0; n < 4; n++)
#pragma unroll
            for (int k = 0; k < 4; k++) accS[n][k] = 0.f;
#pragma unroll
        for (int ks = 0; ks < 4; ks++) {
            uint32_t bb[4][2], t0[4], t1[4];
            ldsm4(t0, sb + koff[0] + ks * 32);
            ldsm4(t1, sb + koff[1] + ks * 32);
            bb[0][0] = t0[0]; bb[0][1] = t0[1];
            bb[1][0] = t0[2]; bb[1][1] = t0[3];
            bb[2][0] = t1[0]; bb[2][1] = t1[1];
            bb[3][0] = t1[2]; bb[3][1] = t1[3];
#pragma unroll
            for (int nt = 0; nt < 4; nt++)
                mma_f16(accS[nt], qf[ks], bb[nt]);
        }

        // ---- local (col-group) row max, shuffles only ----
        float cl = -1e30f, ch = -1e30f;
#pragma unroll
        for (int nt = 0; nt < 4; nt++) {
            cl = fmaxf(cl, fmaxf(accS[nt][0], accS[nt][1]));
            ch = fmaxf(ch, fmaxf(accS[nt][2], accS[nt][3]));
        }
#pragma unroll
        for (int o = 1; o <= 2; o <<= 1) {
            cl = fmaxf(cl, __shfl_xor_sync(0xffffffffu, cl, o));
            ch = fmaxf(ch, __shfl_xor_sync(0xffffffffu, ch, o));
        }
        if (tig == 0) {
            redm[wgrp * FQ + wm + gid] = cl;
            redm[wgrp * FQ + wm + gid + 8] = ch;
        }
        __syncthreads();
        if (c + 1 < NCHUNK) issueK(c + 1);

        float sc[2], nm[2];
#pragma unroll
        for (int h = 0; h < 2; h++) {
            int row = wm + gid + h * 8;
            float mc = fmaxf(redm[row], redm[FQ + row]);
            float mn = fmaxf(mM[h], mc);
            sc[h] = __expf(mM[h] - mn);
            mM[h] = mn;
            nm[h] = -mn * L2E;
        }

        // ---- P = 2^(s*log2e - m*log2e) fp16x2; row sums ----
        float ps[2] = {0.f, 0.f};
        const int prow = (wm + gid) * 36 + wnS / 2;
#pragma unroll
        for (int nt = 0; nt < 4; nt++) {
            uint32_t e01 = ex2_h2(pack2(fmaf(accS[nt][0], L2E, nm[0]),
                                        fmaf(accS[nt][1], L2E, nm[0])));
            uint32_t e23 = ex2_h2(pack2(fmaf(accS[nt][2], L2E, nm[1]),
                                        fmaf(accS[nt][3], L2E, nm[1])));
            __half2 h01 = *reinterpret_cast<__half2*>(&e01);
            __half2 h23 = *reinterpret_cast<__half2*>(&e23);
            ps[0] += __low2float(h01) + __high2float(h01);
            ps[1] += __low2float(h23) + __high2float(h23);
            int w = prow + nt * 4 + tig;
            Pw[w] = e01;
            Pw[w + 8 * 36] = e23;
        }
#pragma unroll
        for (int o = 1; o <= 2; o <<= 1) {
            ps[0] += __shfl_xor_sync(0xffffffffu, ps[0], o);
            ps[1] += __shfl_xor_sync(0xffffffffu, ps[1], o);
        }
        if (tig == 0) {
            reds[wgrp * FQ + wm + gid] = ps[0];
            reds[wgrp * FQ + wm + gid + 8] = ps[1];
        }
        __syncthreads();
#pragma unroll
        for (int h = 0; h < 2; h++) {
            int row = wm + gid + h * 8;
            float su = reds[row] + reds[FQ + row];
            lL[h] = lL[h] * sc[h] + su;
        }

        // ---- rescale accO ----
#pragma unroll
        for (int nt = 0; nt < 16; nt++) {
            accO[nt][0] *= sc[0];
            accO[nt][1] *= sc[0];
            accO[nt][2] *= sc[1];
            accO[nt][3] *= sc[1];
        }

        // ---- wait V(c); barrier publishes P ----
        if (c + 1 < NCHUNK) CP_WAIT1(); else CP_WAIT0();
        __syncthreads();

        // ---- O += P @ V : warp tile 16 x 128 ----
#pragma unroll
        for (int ks = 0; ks < 4; ks++) {
            uint32_t a[4];
            ldsm4(a, sb + poff + ks * 32);
#pragma unroll
            for (int p = 0; p < 8; p++) {
                uint32_t t[4], b0[2], b1[2];
                ldsm4(t, sb + voff[p] + ks * 32);
                b0[0] = t[0]; b0[1] = t[1];
                b1[0] = t[2]; b1[1] = t[3];
                mma_f16(accO[2 * p], a, b0);
                mma_f16(accO[2 * p + 1], a, b1);
            }
        }
        __syncthreads();               // PV done: V and P buffers free
        if (c + 1 < NCHUNK) issueV(c + 1);
    }

    // ---- finalize ----
    {
        float il = 1.f / lL[0], ih = 1.f / lL[1];
        int row = q0 + wm + gid;
#pragma unroll
        for (int nt = 0; nt < 16; nt++) {
            int col = wnP + nt * 8 + 2 * tig;
            *reinterpret_cast<uint32_t*>(&Ob[(long long)row * C2 + col]) =
                pack2(accO[nt][0] * il, accO[nt][1] * il);
            *reinterpret_cast<uint32_t*>(&Ob[(long long)(row + 8) * C2 + col]) =
                pack2(accO[nt][2] * ih, accO[nt][3] * ih);
        }
    }
}

// ---------------------------------------------------------------------------
// x -> fp16
// ---------------------------------------------------------------------------
__global__ void convert_x_kernel(const float* __restrict__ x)
{
    int idx = blockIdx.x * blockDim.x + threadIdx.x;
    const float4 v = reinterpret_cast<const float4*>(x)[idx];
    uint2 u;
    u.x = pack2(v.x, v.y);
    u.y = pack2(v.z, v.w);
    reinterpret_cast<uint2*>(d_Xh)[idx] = u;
}

// ---------------------------------------------------------------------------
// Weights: WcatT [384][512] fp16, WoT [512][256] fp16
// ---------------------------------------------------------------------------
__global__ void concat_w_kernel(const float* __restrict__ wf,
                                const float* __restrict__ wg,
                                const float* __restrict__ wh,
                                const float* __restrict__ wo)
{
    int idx = blockIdx.x * blockDim.x + threadIdx.x;
    const int n1 = NCAT * CC;
    if (idx < n1) {
        int j = idx / CC, k = idx % CC;
        float v;
        if (j < 64)       v = wf[k * C8 + j];
        else if (j < 128) v = wg[k * C8 + (j - 64)];
        else              v = wh[k * C2 + (j - 128)];
        d_WcatT[idx] = __float2half_rn(v);
    } else if (idx < n1 + CC * C2) {
        int i2 = idx - n1;
        int c = i2 / C2, d = i2 % C2;
        d_WoT[i2] = __float2half_rn(wo[d * CC + c]);
    }
}

// ---------------------------------------------------------------------------
// Launch
// ---------------------------------------------------------------------------
extern "C" void kernel_launch(void* const* d_in, const int* in_sizes, int n_in,
                              void* d_out, int out_size)
{
    const float* x     = (const float*)d_in[0];
    const float* wf    = (const float*)d_in[1];
    const float* wg    = (const float*)d_in[2];
    const float* wh    = (const float*)d_in[3];
    const float* wo    = (const float*)d_in[4];
    const float* gamma = (const float*)d_in[5];
    float* out = (float*)d_out;

    cudaFuncSetAttribute(gemm_proj,
                         cudaFuncAttributeMaxDynamicSharedMemorySize, SMEM_TOTAL_G);
    cudaFuncSetAttribute(gemm_out,
                         cudaFuncAttributeMaxDynamicSharedMemorySize, SMEM_TOTAL_G);
    cudaFuncSetAttribute(flash_h,
                         cudaFuncAttributeMaxDynamicSharedMemorySize, FLASH_SMEM);

    // 0) x -> fp16
    convert_x_kernel<<<(BATCH * NPIX * CC / 4 + 255) / 256, 256>>>(x);

    // 1) weights -> fp16 transposed
    concat_w_kernel<<<(NCAT * CC + CC * C2 + 255) / 256, 256>>>(wf, wg, wh, wo);

    // 2+3) projection GEMM with fused pooling epilogue
    gemm_proj<<<dim3(NCAT / 64, (BATCH * NPIX) / 256), 256, SMEM_TOTAL_G>>>();

    // 4-6) fused attention -> Oh fp16
    flash_h<<<dim3(NPIX / FQ, BATCH), 256, FLASH_SMEM>>>();

    // 7) out = gamma * (Oh @ wo) + x
    gemm_out<<<dim3(CC / 64, (BATCH * NPIX) / 256), 256, SMEM_TOTAL_G>>>(x, gamma, out);
}

// round 12
// speedup vs baseline: 1.1745x; 1.0023x over previous
#include <cuda_runtime.h>
#include <cuda_fp16.h>
#include <cstdint>
#include <math.h>

// ---------------------------------------------------------------------------
// Problem constants
// ---------------------------------------------------------------------------
#define BATCH 8
#define WDIM 64
#define CC 512
#define C8 64
#define C2 256
#define NPIX 4096
#define NPOOL 1024
#define NCAT 384

// ---------------------------------------------------------------------------
// Scratch (device globals; allocation-free)
// ---------------------------------------------------------------------------
__device__ __half d_Xh[(long long)BATCH * NPIX * CC];     // 32 MB  x fp16
__device__ __half d_WcatT[NCAT * CC];                     // [384][512]
__device__ __half d_WoT[CC * C2];                         // [512][256]
__device__ __half d_Gh[(long long)BATCH * NPIX * C8];     // 4 MB   g full-res
__device__ __half d_Fh[BATCH * NPOOL * C8];               // 1 MB   pooled f [p][c]
__device__ __half d_Vth[BATCH * C2 * NPOOL];              // 4 MB   pooled h transposed [d][p]
__device__ __half d_Oh[(long long)BATCH * NPIX * C2];     // 16 MB  attention out

// ---------------------------------------------------------------------------
// Helpers
// ---------------------------------------------------------------------------
__device__ __forceinline__ uint32_t smem_u32(const void* p) {
    uint32_t a;
    asm("{ .reg .u64 t; cvta.to.shared.u64 t, %1; cvt.u32.u64 %0, t; }" : "=r"(a) : "l"(p));
    return a;
}
__device__ __forceinline__ void cp16(uint32_t dst, const void* src) {
    asm volatile("cp.async.cg.shared.global [%0], [%1], 16;" ::"r"(dst), "l"(src));
}
#define CP_COMMIT() asm volatile("cp.async.commit_group;" ::: "memory")
#define CP_WAIT0()  asm volatile("cp.async.wait_group 0;" ::: "memory")
#define CP_WAIT1()  asm volatile("cp.async.wait_group 1;" ::: "memory")

__device__ __forceinline__ void mma_f16(float* d, const uint32_t* a, const uint32_t* b) {
    asm volatile(
        "mma.sync.aligned.m16n8k16.row.col.f32.f16.f16.f32 "
        "{%0,%1,%2,%3}, {%4,%5,%6,%7}, {%8,%9}, {%0,%1,%2,%3};"
        : "+f"(d[0]), "+f"(d[1]), "+f"(d[2]), "+f"(d[3])
        : "r"(a[0]), "r"(a[1]), "r"(a[2]), "r"(a[3]), "r"(b[0]), "r"(b[1]));
}
__device__ __forceinline__ void ldsm4(uint32_t* r, uint32_t a) {
    asm volatile("ldmatrix.sync.aligned.m8n8.x4.shared.b16 {%0,%1,%2,%3}, [%4];"
                 : "=r"(r[0]), "=r"(r[1]), "=r"(r[2]), "=r"(r[3]) : "r"(a));
}
__device__ __forceinline__ uint32_t pack2(float x, float y) {
    __half2 h = __floats2half2_rn(x, y);
    return *reinterpret_cast<uint32_t*>(&h);
}
__device__ __forceinline__ uint32_t ex2_h2(uint32_t in) {
    uint32_t r;
    asm("ex2.approx.f16x2 %0, %1;" : "=r"(r) : "r"(in));
    return r;
}
#define L2E 1.4426950408889634f

// ---------------------------------------------------------------------------
// Shared GEMM config: CTA 256x64, BK=32 halfs, 8 warps (4m x 2n), 3 stages.
// ---------------------------------------------------------------------------
#define HSTR 40
#define HASTG (256 * HSTR * 2)
#define HBSTG (64 * HSTR * 2)
#define HGSTG (HASTG + HBSTG)
#define SMEM_TOTAL_G (3 * HGSTG)

// ---------------------------------------------------------------------------
// Projection GEMM + fused 2x2 max-pool epilogue.
// ---------------------------------------------------------------------------
#define CSTR 72

__global__ void __launch_bounds__(256, 2) gemm_proj()
{
    extern __shared__ __align__(16) char smem[];
    const int m0 = blockIdx.y * 256;
    const int n0 = blockIdx.x * 64;
    const int tid = threadIdx.x;
    const int wid = tid >> 5, lane = tid & 31;
    const int gid = lane >> 2, tig = lane & 3;
    const int wm = (wid & 3) * 64;
    const int wn = (wid >> 2) * 32;

    const __half* A = d_Xh;
    const __half* Bt = d_WcatT;
    const uint32_t sb = smem_u32(smem);
    const int KT = CC / 32;

    const int arow = lane & 15;
    const int acol = (lane >> 4) << 4;
    const int brow = (lane & 7) + ((lane >> 4) & 1) * 8;
    const int bcol = ((lane >> 3) & 1) << 4;
    uint32_t aoff[4], boff[2];
#pragma unroll
    for (int mt = 0; mt < 4; mt++) aoff[mt] = (uint32_t)((wm + mt * 16 + arow) * 80 + acol);
#pragma unroll
    for (int p = 0; p < 2; p++) boff[p] = (uint32_t)(HASTG + (wn + p * 16 + brow) * 80 + bcol);

    auto issue = [&](int kt, int s) {
        const uint32_t aB = sb + (uint32_t)(s * HGSTG);
        const uint32_t bB = aB + HASTG;
#pragma unroll
        for (int it = 0; it < 4; it++) {
            int idx = tid + it * 256;
            int r = idx >> 2, q = idx & 3;
            cp16(aB + (uint32_t)(r * 80 + q * 16),
                 A + (long long)(m0 + r) * CC + kt * 32 + q * 8);
        }
        {
            int r = tid >> 2, q = tid & 3;
            cp16(bB + (uint32_t)(r * 80 + q * 16),
                 Bt + (long long)(n0 + r) * CC + kt * 32 + q * 8);
        }
        CP_COMMIT();
    };

    float acc[4][4][4];
#pragma unroll
    for (int i = 0; i < 4; i++)
#pragma unroll
        for (int j = 0; j < 4; j++)
#pragma unroll
            for (int k = 0; k < 4; k++) acc[i][j][k] = 0.f;

    issue(0, 0);
    issue(1, 1);

    for (int kt = 0; kt < KT; kt++) {
        const int s = kt % 3;
        if (kt < KT - 1) CP_WAIT1(); else CP_WAIT0();
        __syncthreads();
        if (kt + 2 < KT) issue(kt + 2, (kt + 2) % 3);

        const uint32_t stB = sb + (uint32_t)(s * HGSTG);
#pragma unroll
        for (int ks = 0; ks < 2; ks++) {
            uint32_t a[4][4], b[4][2];
#pragma unroll
            for (int mt = 0; mt < 4; mt++) ldsm4(a[mt], stB + aoff[mt] + ks * 32);
#pragma unroll
            for (int p = 0; p < 2; p++) {
                uint32_t t[4];
                ldsm4(t, stB + boff[p] + ks * 32);
                b[2 * p][0] = t[0]; b[2 * p][1] = t[1];
                b[2 * p + 1][0] = t[2]; b[2 * p + 1][1] = t[3];
            }
#pragma unroll
            for (int mt = 0; mt < 4; mt++)
#pragma unroll
                for (int nt = 0; nt < 4; nt++)
                    mma_f16(acc[mt][nt], a[mt], b[nt]);
        }
    }

    __syncthreads();
    uint32_t* Cw = (uint32_t*)smem;
#pragma unroll
    for (int mt = 0; mt < 4; mt++)
#pragma unroll
        for (int h = 0; h < 2; h++) {
            int row = wm + mt * 16 + gid + h * 8;
#pragma unroll
            for (int nt = 0; nt < 4; nt++)
                Cw[row * (CSTR / 2) + wn / 2 + nt * 4 + tig] =
                    pack2(acc[mt][nt][h * 2], acc[mt][nt][h * 2 + 1]);
        }
    __syncthreads();

    const __half* Cs = (const __half*)smem;
    const int b = m0 >> 12;
    const int pix0 = m0 & 4095;
    const int pr0 = pix0 >> 7;

    if (n0 == 64) {
        __half* G = d_Gh + (long long)m0 * C8;
#pragma unroll
        for (int it = 0; it < 8; it++) {
            int idx = tid + it * 256;
            int row = idx >> 3, q = idx & 7;
            uint4 v = *reinterpret_cast<const uint4*>(&Cw[row * (CSTR / 2) + q * 4]);
            *reinterpret_cast<uint4*>(&G[row * C8 + q * 8]) = v;
        }
    } else if (n0 == 0) {
        __half* F = d_Fh + (b * NPOOL + pr0 * 32) * C8;
        const __half2* C2s = (const __half2*)Cs;
#pragma unroll
        for (int it = 0; it < 8; it++) {
            int idx = tid + it * 256;
            int p = idx >> 5, c2 = idx & 31;
            int base = ((p >> 5) * 2) * 64 + (p & 31) * 2;
            __half2 v0 = C2s[(base) * (CSTR / 2) + c2];
            __half2 v1 = C2s[(base + 1) * (CSTR / 2) + c2];
            __half2 v2 = C2s[(base + 64) * (CSTR / 2) + c2];
            __half2 v3 = C2s[(base + 65) * (CSTR / 2) + c2];
            __half2 v = __hmax2(__hmax2(v0, v1), __hmax2(v2, v3));
            *reinterpret_cast<__half2*>(&F[p * C8 + 2 * c2]) = v;
        }
    } else {
        int c = tid & 63;
        int pgrp = tid >> 6;
        int d = n0 - 128 + c;
        __half buf[16];
#pragma unroll
        for (int j = 0; j < 16; j++) {
            int p = pgrp * 16 + j;
            int base = ((p >> 5) * 2) * 64 + (p & 31) * 2;
            __half v0 = Cs[(base) * CSTR + c];
            __half v1 = Cs[(base + 1) * CSTR + c];
            __half v2 = Cs[(base + 64) * CSTR + c];
            __half v3 = Cs[(base + 65) * CSTR + c];
            buf[j] = __hmax(__hmax(v0, v1), __hmax(v2, v3));
        }
        __half* dst = d_Vth + ((long long)b * C2 + d) * NPOOL + pr0 * 32 + pgrp * 16;
        *reinterpret_cast<uint4*>(dst) = *reinterpret_cast<uint4*>(buf);
        *reinterpret_cast<uint4*>(dst + 8) = *reinterpret_cast<uint4*>(buf + 8);
    }
}

// ---------------------------------------------------------------------------
// Output GEMM: out = gamma * (Oh @ WoT^T) + x   (M=32768, N=512, K=256)
// ---------------------------------------------------------------------------
__global__ void __launch_bounds__(256, 2) gemm_out(
    const float* __restrict__ resid, const float* __restrict__ gamma,
    float* __restrict__ C)
{
    extern __shared__ __align__(16) char smem[];
    const int m0 = blockIdx.y * 256;
    const int n0 = blockIdx.x * 64;
    const int tid = threadIdx.x;
    const int wid = tid >> 5, lane = tid & 31;
    const int gid = lane >> 2, tig = lane & 3;
    const int wm = (wid & 3) * 64;
    const int wn = (wid >> 2) * 32;

    const __half* A = d_Oh;
    const __half* Bt = d_WoT;
    const uint32_t sb = smem_u32(smem);
    const int KT = C2 / 32;

    const int arow = lane & 15;
    const int acol = (lane >> 4) << 4;
    const int brow = (lane & 7) + ((lane >> 4) & 1) * 8;
    const int bcol = ((lane >> 3) & 1) << 4;
    uint32_t aoff[4], boff[2];
#pragma unroll
    for (int mt = 0; mt < 4; mt++) aoff[mt] = (uint32_t)((wm + mt * 16 + arow) * 80 + acol);
#pragma unroll
    for (int p = 0; p < 2; p++) boff[p] = (uint32_t)(HASTG + (wn + p * 16 + brow) * 80 + bcol);

    auto issue = [&](int kt, int s) {
        const uint32_t aB = sb + (uint32_t)(s * HGSTG);
        const uint32_t bB = aB + HASTG;
#pragma unroll
        for (int it = 0; it < 4; it++) {
            int idx = tid + it * 256;
            int r = idx >> 2, q = idx & 3;
            cp16(aB + (uint32_t)(r * 80 + q * 16),
                 A + (long long)(m0 + r) * C2 + kt * 32 + q * 8);
        }
        {
            int r = tid >> 2, q = tid & 3;
            cp16(bB + (uint32_t)(r * 80 + q * 16),
                 Bt + (long long)(n0 + r) * C2 + kt * 32 + q * 8);
        }
        CP_COMMIT();
    };

    float acc[4][4][4];
#pragma unroll
    for (int i = 0; i < 4; i++)
#pragma unroll
        for (int j = 0; j < 4; j++)
#pragma unroll
            for (int k = 0; k < 4; k++) acc[i][j][k] = 0.f;

    issue(0, 0);
    issue(1, 1);

    for (int kt = 0; kt < KT; kt++) {
        const int s = kt % 3;
        if (kt < KT - 1) CP_WAIT1(); else CP_WAIT0();
        __syncthreads();
        if (kt + 2 < KT) issue(kt + 2, (kt + 2) % 3);

        const uint32_t stB = sb + (uint32_t)(s * HGSTG);
#pragma unroll
        for (int ks = 0; ks < 2; ks++) {
            uint32_t a[4][4], b[4][2];
#pragma unroll
            for (int mt = 0; mt < 4; mt++) ldsm4(a[mt], stB + aoff[mt] + ks * 32);
#pragma unroll
            for (int p = 0; p < 2; p++) {
                uint32_t t[4];
                ldsm4(t, stB + boff[p] + ks * 32);
                b[2 * p][0] = t[0]; b[2 * p][1] = t[1];
                b[2 * p + 1][0] = t[2]; b[2 * p + 1][1] = t[3];
            }
#pragma unroll
            for (int mt = 0; mt < 4; mt++)
#pragma unroll
                for (int nt = 0; nt < 4; nt++)
                    mma_f16(acc[mt][nt], a[mt], b[nt]);
        }
    }

    const float gm = gamma[0];
#pragma unroll
    for (int mt = 0; mt < 4; mt++)
#pragma unroll
        for (int h = 0; h < 2; h++) {
            long long row = m0 + wm + mt * 16 + gid + h * 8;
#pragma unroll
            for (int nt = 0; nt < 4; nt++) {
                long long off = row * CC + n0 + wn + nt * 8 + 2 * tig;
                float2 rv = *reinterpret_cast<const float2*>(&resid[off]);
                float2 v;
                v.x = fmaf(gm, acc[mt][nt][h * 2], rv.x);
                v.y = fmaf(gm, acc[mt][nt][h * 2 + 1], rv.y);
                *reinterpret_cast<float2*>(&C[off]) = v;
            }
        }
}

// ---------------------------------------------------------------------------
// Flash attention: 256 thr / 64 q per CTA, 2 CTAs/SM, 16 chunks of 64 keys.
// DOUBLE-BUFFERED K and V; K(c+1)+V(c+1) issued as one group at top of chunk
// c (full-chunk prefetch cover). 1 cp-wait + 3 barriers per chunk.
// Smem/CTA = 109 KB: Q 9K | P 9K | K 2x9K | V 2x36K | stats 1K.
// ---------------------------------------------------------------------------
#define FQ 64
#define NCHUNK 16
#define SM_Q 0
#define SM_P 9216
#define SM_K 18432
#define SM_V 36864
#define SM_RM 110592
#define SM_RS 111104
#define FLASH_SMEM 111616

__global__ void __launch_bounds__(256, 2) flash_h()
{
    extern __shared__ __align__(16) char fsm[];
    const uint32_t sb = smem_u32(fsm);

    const int b = blockIdx.y;
    const int q0 = blockIdx.x * FQ;
    const __half* Qg = d_Gh + ((long long)b * NPIX + q0) * C8;
    const __half* Fb = d_Fh + b * NPOOL * C8;
    const __half* Vtb = d_Vth + (long long)b * C2 * NPOOL;
    __half* Ob = d_Oh + (long long)b * NPIX * C2;

    const int tid = threadIdx.x;
    const int wid = tid >> 5, lane = tid & 31;
    const int gid = lane >> 2, tig = lane & 3;
    const int wm = (wid & 3) * 16;     // 4 m-groups x 16 rows
    const int wgrp = wid >> 2;         // 2 col-groups
    const int wnS = wgrp * 32;         // keys 0-31 / 32-63
    const int wnP = wgrp * 128;        // PV cols

    const int arow = lane & 15;
    const int acol = (lane >> 4) << 4;
    const int brow = (lane & 7) + ((lane >> 4) & 1) * 8;
    const int bcol = ((lane >> 3) & 1) << 4;
    const uint32_t qoff = (uint32_t)(SM_Q + (wm + arow) * 144 + acol);
    const uint32_t poff = (uint32_t)(SM_P + (wm + arow) * 144 + acol);
    uint32_t koff[2], voff[8];
#pragma unroll
    for (int k16 = 0; k16 < 2; k16++)
        koff[k16] = (uint32_t)(SM_K + (wnS + k16 * 16 + brow) * 144 + bcol);
#pragma unroll
    for (int p = 0; p < 8; p++)
        voff[p] = (uint32_t)(SM_V + (wnP + p * 16 + brow) * 144 + bcol);

    // K(c)+V(c) -> buffer c&1, one commit group
    auto issueKV = [&](int c) {
        const uint32_t kb = sb + SM_K + (uint32_t)((c & 1) * 9216);
        const uint32_t vb = sb + SM_V + (uint32_t)((c & 1) * 36864);
#pragma unroll
        for (int it = 0; it < 2; it++) {
            int idx = tid + it * 256;
            int r = idx >> 3, q = idx & 7;
            cp16(kb + (uint32_t)(r * 144 + q * 16),
                 Fb + (c * 64 + r) * C8 + q * 8);
        }
#pragma unroll
        for (int it = 0; it < 8; it++) {
            int idx = tid + it * 256;
            int r = idx >> 3, q = idx & 7;
            cp16(vb + (uint32_t)(r * 144 + q * 16),
                 Vtb + (long long)r * NPOOL + c * 64 + q * 8);
        }
        CP_COMMIT();
    };

    // prologue: Q + K0 + V0, one group
    {
#pragma unroll
        for (int it = 0; it < 2; it++) {
            int idx = tid + it * 256;
            int r = idx >> 3, q = idx & 7;
            cp16(sb + SM_Q + (uint32_t)(r * 144 + q * 16),
                 Qg + (long long)r * C8 + q * 8);
        }
        issueKV(0);   // commits Q + K0 + V0
    }
    CP_WAIT0();
    __syncthreads();
    uint32_t qf[4][4];
#pragma unroll
    for (int ks = 0; ks < 4; ks++) ldsm4(qf[ks], sb + qoff + ks * 32);

    float accO[16][4];
#pragma unroll
    for (int n = 0; n < 16; n++)
#pragma unroll
        for (int k = 0; k < 4; k++) accO[n][k] = 0.f;
    float mM[2] = {-1e30f, -1e30f};
    float lL[2] = {0.f, 0.f};

    uint32_t* Pw = (uint32_t*)(fsm + SM_P);
    float* redm = (float*)(fsm + SM_RM);
    float* reds = (float*)(fsm + SM_RS);

    for (int c = 0; c < NCHUNK; c++) {
        const uint32_t sK = (uint32_t)((c & 1) * 9216);
        const uint32_t sV = (uint32_t)((c & 1) * 36864);

        if (c) {
            CP_WAIT0();                // K(c)+V(c) landed
            __syncthreads();           // all threads' data visible; buf c+1&1 free
        }
        if (c + 1 < NCHUNK) issueKV(c + 1);

        // ---- S = Q @ F^T : warp tile 16q x 32k ----
        float accS[4][4];
#pragma unroll
        for (int n = 0; n < 4; n++)
#pragma unroll
            for (int k = 0; k < 4; k++) accS[n][k] = 0.f;
#pragma unroll
        for (int ks = 0; ks < 4; ks++) {
            uint32_t bb[4][2], t0[4], t1[4];
            ldsm4(t0, sb + sK + koff[0] + ks * 32);
            ldsm4(t1, sb + sK + koff[1] + ks * 32);
            bb[0][0] = t0[0]; bb[0][1] = t0[1];
            bb[1][0] = t0[2]; bb[1][1] = t0[3];
            bb[2][0] = t1[0]; bb[2][1] = t1[1];
            bb[3][0] = t1[2]; bb[3][1] = t1[3];
#pragma unroll
            for (int nt = 0; nt < 4; nt++)
                mma_f16(accS[nt], qf[ks], bb[nt]);
        }

        // ---- local (col-group) row max, shuffles only ----
        float cl = -1e30f, ch = -1e30f;
#pragma unroll
        for (int nt = 0; nt < 4; nt++) {
            cl = fmaxf(cl, fmaxf(accS[nt][0], accS[nt][1]));
            ch = fmaxf(ch, fmaxf(accS[nt][2], accS[nt][3]));
        }
#pragma unroll
        for (int o = 1; o <= 2; o <<= 1) {
            cl = fmaxf(cl, __shfl_xor_sync(0xffffffffu, cl, o));
            ch = fmaxf(ch, __shfl_xor_sync(0xffffffffu, ch, o));
        }
        if (tig == 0) {
            redm[wgrp * FQ + wm + gid] = cl;
            redm[wgrp * FQ + wm + gid + 8] = ch;
        }
        __syncthreads();

        float sc[2], nm[2];
#pragma unroll
        for (int h = 0; h < 2; h++) {
            int row = wm + gid + h * 8;
            float mc = fmaxf(redm[row], redm[FQ + row]);
            float mn = fmaxf(mM[h], mc);
            sc[h] = __expf(mM[h] - mn);
            mM[h] = mn;
            nm[h] = -mn * L2E;
        }

        // ---- P = 2^(s*log2e - m*log2e) fp16x2; row sums ----
        float ps[2] = {0.f, 0.f};
        const int prow = (wm + gid) * 36 + wnS / 2;
#pragma unroll
        for (int nt = 0; nt < 4; nt++) {
            uint32_t e01 = ex2_h2(pack2(fmaf(accS[nt][0], L2E, nm[0]),
                                        fmaf(accS[nt][1], L2E, nm[0])));
            uint32_t e23 = ex2_h2(pack2(fmaf(accS[nt][2], L2E, nm[1]),
                                        fmaf(accS[nt][3], L2E, nm[1])));
            __half2 h01 = *reinterpret_cast<__half2*>(&e01);
            __half2 h23 = *reinterpret_cast<__half2*>(&e23);
            ps[0] += __low2float(h01) + __high2float(h01);
            ps[1] += __low2float(h23) + __high2float(h23);
            int w = prow + nt * 4 + tig;
            Pw[w] = e01;
            Pw[w + 8 * 36] = e23;
        }
#pragma unroll
        for (int o = 1; o <= 2; o <<= 1) {
            ps[0] += __shfl_xor_sync(0xffffffffu, ps[0], o);
            ps[1] += __shfl_xor_sync(0xffffffffu, ps[1], o);
        }
        if (tig == 0) {
            reds[wgrp * FQ + wm + gid] = ps[0];
            reds[wgrp * FQ + wm + gid + 8] = ps[1];
        }
        __syncthreads();               // stats + P visible
#pragma unroll
        for (int h = 0; h < 2; h++) {
            int row = wm + gid + h * 8;
            float su = reds[row] + reds[FQ + row];
            lL[h] = lL[h] * sc[h] + su;
        }

        // ---- rescale accO ----
#pragma unroll
        for (int nt = 0; nt < 16; nt++) {
            accO[nt][0] *= sc[0];
            accO[nt][1] *= sc[0];
            accO[nt][2] *= sc[1];
            accO[nt][3] *= sc[1];
        }

        // ---- O += P @ V : warp tile 16 x 128 (V already waited at top) ----
#pragma unroll
        for (int ks = 0; ks < 4; ks++) {
            uint32_t a[4];
            ldsm4(a, sb + poff + ks * 32);
#pragma unroll
            for (int p = 0; p < 8; p++) {
                uint32_t t[4], b0[2], b1[2];
                ldsm4(t, sb + sV + voff[p] + ks * 32);
                b0[0] = t[0]; b0[1] = t[1];
                b1[0] = t[2]; b1[1] = t[3];
                mma_f16(accO[2 * p], a, b0);
                mma_f16(accO[2 * p + 1], a, b1);
            }
        }
        // no end barrier: next chunk's top sync covers P reuse + buffer swap
    }

    // ---- finalize ----
    {
        float il = 1.f / lL[0], ih = 1.f / lL[1];
        int row = q0 + wm + gid;
#pragma unroll
        for (int nt = 0; nt < 16; nt++) {
            int col = wnP + nt * 8 + 2 * tig;
            *reinterpret_cast<uint32_t*>(&Ob[(long long)row * C2 + col]) =
                pack2(accO[nt][0] * il, accO[nt][1] * il);
            *reinterpret_cast<uint32_t*>(&Ob[(long long)(row + 8) * C2 + col]) =
                pack2(accO[nt][2] * ih, accO[nt][3] * ih);
        }
    }
}

// ---------------------------------------------------------------------------
// x -> fp16
// ---------------------------------------------------------------------------
__global__ void convert_x_kernel(const float* __restrict__ x)
{
    int idx = blockIdx.x * blockDim.x + threadIdx.x;
    const float4 v = reinterpret_cast<const float4*>(x)[idx];
    uint2 u;
    u.x = pack2(v.x, v.y);
    u.y = pack2(v.z, v.w);
    reinterpret_cast<uint2*>(d_Xh)[idx] = u;
}

// ---------------------------------------------------------------------------
// Weights: WcatT [384][512] fp16, WoT [512][256] fp16
// ---------------------------------------------------------------------------
__global__ void concat_w_kernel(const float* __restrict__ wf,
                                const float* __restrict__ wg,
                                const float* __restrict__ wh,
                                const float* __restrict__ wo)
{
    int idx = blockIdx.x * blockDim.x + threadIdx.x;
    const int n1 = NCAT * CC;
    if (idx < n1) {
        int j = idx / CC, k = idx % CC;
        float v;
        if (j < 64)       v = wf[k * C8 + j];
        else if (j < 128) v = wg[k * C8 + (j - 64)];
        else              v = wh[k * C2 + (j - 128)];
        d_WcatT[idx] = __float2half_rn(v);
    } else if (idx < n1 + CC * C2) {
        int i2 = idx - n1;
        int c = i2 / C2, d = i2 % C2;
        d_WoT[i2] = __float2half_rn(wo[d * CC + c]);
    }
}

// ---------------------------------------------------------------------------
// Launch
// ---------------------------------------------------------------------------
extern "C" void kernel_launch(void* const* d_in, const int* in_sizes, int n_in,
                              void* d_out, int out_size)
{
    const float* x     = (const float*)d_in[0];
    const float* wf    = (const float*)d_in[1];
    const float* wg    = (const float*)d_in[2];
    const float* wh    = (const float*)d_in[3];
    const float* wo    = (const float*)d_in[4];
    const float* gamma = (const float*)d_in[5];
    float* out = (float*)d_out;

    cudaFuncSetAttribute(gemm_proj,
                         cudaFuncAttributeMaxDynamicSharedMemorySize, SMEM_TOTAL_G);
    cudaFuncSetAttribute(gemm_out,
                         cudaFuncAttributeMaxDynamicSharedMemorySize, SMEM_TOTAL_G);
    cudaFuncSetAttribute(flash_h,
                         cudaFuncAttributeMaxDynamicSharedMemorySize, FLASH_SMEM);

    // 0) x -> fp16
    convert_x_kernel<<<(BATCH * NPIX * CC / 4 + 255) / 256, 256>>>(x);

    // 1) weights -> fp16 transposed
    concat_w_kernel<<<(NCAT * CC + CC * C2 + 255) / 256, 256>>>(wf, wg, wh, wo);

    // 2+3) projection GEMM with fused pooling epilogue
    gemm_proj<<<dim3(NCAT / 64, (BATCH * NPIX) / 256), 256, SMEM_TOTAL_G>>>();

    // 4-6) fused attention -> Oh fp16
    flash_h<<<dim3(NPIX / FQ, BATCH), 256, FLASH_SMEM>>>();

    // 7) out = gamma * (Oh @ wo) + x
    gemm_out<<<dim3(CC / 64, (BATCH * NPIX) / 256), 256, SMEM_TOTAL_G>>>(x, gamma, out);
}